// round 11
// baseline (speedup 1.0000x reference)
#include <cuda_runtime.h>
#include <cuda_bf16.h>
#include <math.h>
#include <stdint.h>

#define NB 32
#define LL 1024
#define DD 256
#define HH 256
typedef __nv_bfloat16 bf16;

#define NXD ((size_t)NB * LL * DD)
#define NE  ((size_t)NB * LL * LL)

// ---------------------------------------------------------------------------
// Device scratch
// ---------------------------------------------------------------------------
__device__ __align__(256) bf16 g_Xp_hi[NXD], g_Xp_lo[NXD];
__device__ __align__(256) bf16 g_Xh_hi[NXD], g_Xh_lo[NXD];
__device__ __align__(256) bf16 g_Wt_hi[DD * HH], g_Wt_lo[DD * HH];
__device__ __align__(256) bf16 g_Fp_hi[NXD], g_Fp_lo[NXD];
__device__ __align__(256) bf16 g_Fh_hi[NXD], g_Fh_lo[NXD];
__device__ __align__(256) bf16 g_Ht_hi[NXD], g_Ht_lo[NXD];
__device__ __align__(256) bf16 g_Pt_hi[NXD], g_Pt_lo[NXD];
__device__ __align__(256) float g_E[NE];
__device__ __align__(256) bf16 g_Tr_hi[NE], g_Tr_lo[NE];
__device__ __align__(256) float g_rowmax[NB * LL], g_rowsum[NB * LL], g_colsum[NB * LL];
__device__ __align__(256) float g_Mb[NB];

// ---------------------------------------------------------------------------
// helpers
// ---------------------------------------------------------------------------
__device__ __forceinline__ uint32_t smem_u32(const void* p) {
    uint32_t a;
    asm("{ .reg .u64 t; cvta.to.shared.u64 t, %1; cvt.u32.u64 %0, t; }" : "=r"(a) : "l"(p));
    return a;
}
__device__ __forceinline__ void cp_async16(uint32_t dst, const void* src) {
    asm volatile("cp.async.cg.shared.global [%0], [%1], 16;" :: "r"(dst), "l"(src));
}
__device__ __forceinline__ void ldsm4(uint32_t& r0, uint32_t& r1, uint32_t& r2,
                                      uint32_t& r3, uint32_t addr) {
    asm volatile("ldmatrix.sync.aligned.m8n8.x4.shared.b16 {%0,%1,%2,%3}, [%4];"
                 : "=r"(r0), "=r"(r1), "=r"(r2), "=r"(r3) : "r"(addr));
}
__device__ __forceinline__ void ldsm4t(uint32_t& r0, uint32_t& r1, uint32_t& r2,
                                       uint32_t& r3, uint32_t addr) {
    asm volatile("ldmatrix.sync.aligned.m8n8.x4.trans.shared.b16 {%0,%1,%2,%3}, [%4];"
                 : "=r"(r0), "=r"(r1), "=r"(r2), "=r"(r3) : "r"(addr));
}
__device__ __forceinline__ void mma_bf16(float* c, const uint32_t* a, uint32_t b0, uint32_t b1) {
    asm volatile(
        "mma.sync.aligned.m16n8k16.row.col.f32.bf16.bf16.f32 "
        "{%0,%1,%2,%3}, {%4,%5,%6,%7}, {%8,%9}, {%0,%1,%2,%3};"
        : "+f"(c[0]), "+f"(c[1]), "+f"(c[2]), "+f"(c[3])
        : "r"(a[0]), "r"(a[1]), "r"(a[2]), "r"(a[3]), "r"(b0), "r"(b1));
}
__device__ __forceinline__ void atomicMaxF(float* a, float v) {
    if (v >= 0.f) atomicMax((int*)a, __float_as_int(v));
    else          atomicMin((unsigned int*)a, __float_as_uint(v));
}

// ---------------------------------------------------------------------------
// Split-bf16 warp-MMA GEMM (normal A): C[m,n] = sum_k A[m,k]*B[n,k]
// 3 passes (hh, h*Blo, Alo*h) in register acc. CTA 128x128, BK=32, cp.async
// double-buffered. epi: 0 fp32 C (+opt rowmax atomics); 1 tanh->split bf16;
// 2 scale 1/scale[b*mpb+m].
// ---------------------------------------------------------------------------
__global__ __launch_bounds__(256) void gemm_split(
    const bf16* __restrict__ Ahi, const bf16* __restrict__ Alo, size_t a_bs, int lda,
    const bf16* __restrict__ Bhi, const bf16* __restrict__ Blo, size_t b_bs, int ldb,
    int K, int epi,
    float* __restrict__ C, size_t c_bs, int ldc,
    const float* __restrict__ scale, int mpb,
    bf16* __restrict__ Fhi, bf16* __restrict__ Flo,
    float* __restrict__ rmaxAt)
{
    __shared__ __align__(16) uint8_t sm[2 * 20480];   // [stage][A 10240 | B 10240]
    const uint32_t smb = smem_u32(sm);
    const int tid = threadIdx.x, lane = tid & 31, wid = tid >> 5;
    const int wm = wid & 3, wn = wid >> 2;
    const int bm = blockIdx.x * 128, bn = blockIdx.y * 128, b = blockIdx.z;
    const int nk = K >> 5, nch = 3 * nk;

    const int r0s = tid >> 2,          kv0 = (tid & 3) * 8;
    const int r1s = (tid + 256) >> 2,  kv1 = ((tid + 256) & 3) * 8;

    auto issue = [&](int ch, int st) {
        const int pass = ch / nk;
        const int k0 = (ch - pass * nk) << 5;
        const bf16* Ap = (pass == 2 ? Alo : Ahi) + (size_t)b * a_bs;
        const bf16* Bp = (pass == 1 ? Blo : Bhi) + (size_t)b * b_bs;
        uint32_t da = smb + (uint32_t)st * 20480;
        uint32_t db = da + 10240;
        cp_async16(da + r0s * 80 + kv0 * 2, Ap + (size_t)(bm + r0s) * lda + k0 + kv0);
        cp_async16(da + r1s * 80 + kv1 * 2, Ap + (size_t)(bm + r1s) * lda + k0 + kv1);
        cp_async16(db + r0s * 80 + kv0 * 2, Bp + (size_t)(bn + r0s) * ldb + k0 + kv0);
        cp_async16(db + r1s * 80 + kv1 * 2, Bp + (size_t)(bn + r1s) * ldb + k0 + kv1);
        asm volatile("cp.async.commit_group;");
    };

    float acc[2][8][4] = {};
    issue(0, 0);
    for (int ch = 0; ch < nch; ch++) {
        const int st = ch & 1;
        if (ch + 1 < nch) { issue(ch + 1, st ^ 1); asm volatile("cp.async.wait_group 1;"); }
        else              { asm volatile("cp.async.wait_group 0;"); }
        __syncthreads();
        const uint32_t sAb = smb + (uint32_t)st * 20480;
        const uint32_t sBb = sAb + 10240;
        #pragma unroll
        for (int ks = 0; ks < 2; ks++) {
            const uint32_t colb = (uint32_t)(ks * 16 + (lane >> 4) * 8) * 2;
            uint32_t a[2][4];
            #pragma unroll
            for (int fm = 0; fm < 2; fm++) {
                uint32_t ad = sAb + (uint32_t)(wm * 32 + fm * 16 + (lane & 15)) * 80 + colb;
                ldsm4(a[fm][0], a[fm][1], a[fm][2], a[fm][3], ad);
            }
            uint32_t bb[4][4];
            #pragma unroll
            for (int fn = 0; fn < 4; fn++) {
                uint32_t bd = sBb + (uint32_t)(wn * 64 + fn * 16 + (lane & 15)) * 80 + colb;
                ldsm4(bb[fn][0], bb[fn][1], bb[fn][2], bb[fn][3], bd);
            }
            #pragma unroll
            for (int fm = 0; fm < 2; fm++)
                #pragma unroll
                for (int fn = 0; fn < 4; fn++) {
                    mma_bf16(acc[fm][fn * 2],     a[fm], bb[fn][0], bb[fn][2]);
                    mma_bf16(acc[fm][fn * 2 + 1], a[fm], bb[fn][1], bb[fn][3]);
                }
        }
        __syncthreads();
    }

    const int fr = lane >> 2;
    const int fc = (lane & 3) * 2;
    if (rmaxAt) {
        #pragma unroll
        for (int fm = 0; fm < 2; fm++)
            #pragma unroll
            for (int half = 0; half < 2; half++) {
                float m = -INFINITY;
                #pragma unroll
                for (int fn = 0; fn < 8; fn++) {
                    m = fmaxf(m, acc[fm][fn][half * 2]);
                    m = fmaxf(m, acc[fm][fn][half * 2 + 1]);
                }
                m = fmaxf(m, __shfl_xor_sync(~0u, m, 1));
                m = fmaxf(m, __shfl_xor_sync(~0u, m, 2));
                if ((lane & 3) == 0)
                    atomicMaxF(rmaxAt + (size_t)b * mpb + bm + wm * 32 + fm * 16 + fr + half * 8, m);
            }
    }
    #pragma unroll
    for (int fm = 0; fm < 2; fm++) {
        const int row0 = bm + wm * 32 + fm * 16 + fr;
        if (epi == 1) {
            #pragma unroll
            for (int half = 0; half < 2; half++) {
                const size_t gr = (size_t)(row0 + half * 8);
                #pragma unroll
                for (int fn = 0; fn < 8; fn++) {
                    const int col = bn + wn * 64 + fn * 8 + fc;
                    float v0 = tanhf(acc[fm][fn][half * 2]);
                    float v1 = tanhf(acc[fm][fn][half * 2 + 1]);
                    bf16 h0 = __float2bfloat16(v0), h1 = __float2bfloat16(v1);
                    __nv_bfloat162 hp, lp;
                    hp.x = h0; hp.y = h1;
                    lp.x = __float2bfloat16(v0 - __bfloat162float(h0));
                    lp.y = __float2bfloat16(v1 - __bfloat162float(h1));
                    size_t o = gr * ldc + col;
                    *(__nv_bfloat162*)(Fhi + o) = hp;
                    *(__nv_bfloat162*)(Flo + o) = lp;
                }
            }
        } else {
            float s0 = 1.f, s1 = 1.f;
            if (epi == 2) {
                s0 = 1.0f / scale[(size_t)b * mpb + row0];
                s1 = 1.0f / scale[(size_t)b * mpb + row0 + 8];
            }
            float* Cb = C + (size_t)b * c_bs;
            #pragma unroll
            for (int fn = 0; fn < 8; fn++) {
                const int col = bn + wn * 64 + fn * 8 + fc;
                float2 v0, v1;
                v0.x = acc[fm][fn][0] * s0; v0.y = acc[fm][fn][1] * s0;
                v1.x = acc[fm][fn][2] * s1; v1.y = acc[fm][fn][3] * s1;
                *(float2*)(Cb + (size_t)row0 * ldc + col) = v0;
                *(float2*)(Cb + (size_t)(row0 + 8) * ldc + col) = v1;
            }
        }
    }
}

// ---------------------------------------------------------------------------
// Trans-A variant (alphas): C[m,n] = sum_k A[k,m]*B[n,k]  (A read transposed
// via ldmatrix.trans). A tile [32k x 128m] pitch 272B, B tile [128n x 32k]
// pitch 80B. Scaled fp32 output.
// ---------------------------------------------------------------------------
__global__ __launch_bounds__(256) void gemm_splitT(
    const bf16* __restrict__ Ahi, const bf16* __restrict__ Alo, size_t a_bs, int lda,
    const bf16* __restrict__ Bhi, const bf16* __restrict__ Blo, size_t b_bs, int ldb,
    int K,
    float* __restrict__ C, size_t c_bs, int ldc,
    const float* __restrict__ scale, int mpb)
{
    __shared__ __align__(16) uint8_t sm[2 * 18944];   // [stage][A 8704 | B 10240]
    const uint32_t smb = smem_u32(sm);
    const int tid = threadIdx.x, lane = tid & 31, wid = tid >> 5;
    const int wm = wid & 3, wn = wid >> 2;
    const int bm = blockIdx.x * 128, bn = blockIdx.y * 128, b = blockIdx.z;
    const int nk = K >> 5, nch = 3 * nk;

    // A: 32 k-rows x 128 m-cols = 512 chunks -> 2 per thread
    const int ar  = tid >> 4,          akv = (tid & 15) * 8;
    const int r0s = tid >> 2,          kv0 = (tid & 3) * 8;
    const int r1s = (tid + 256) >> 2,  kv1 = ((tid + 256) & 3) * 8;

    auto issue = [&](int ch, int st) {
        const int pass = ch / nk;
        const int k0 = (ch - pass * nk) << 5;
        const bf16* Ap = (pass == 2 ? Alo : Ahi) + (size_t)b * a_bs;
        const bf16* Bp = (pass == 1 ? Blo : Bhi) + (size_t)b * b_bs;
        uint32_t da = smb + (uint32_t)st * 18944;
        uint32_t db = da + 8704;
        cp_async16(da + ar * 272 + akv * 2,
                   Ap + (size_t)(k0 + ar) * lda + bm + akv);
        cp_async16(da + (ar + 16) * 272 + akv * 2,
                   Ap + (size_t)(k0 + ar + 16) * lda + bm + akv);
        cp_async16(db + r0s * 80 + kv0 * 2, Bp + (size_t)(bn + r0s) * ldb + k0 + kv0);
        cp_async16(db + r1s * 80 + kv1 * 2, Bp + (size_t)(bn + r1s) * ldb + k0 + kv1);
        asm volatile("cp.async.commit_group;");
    };

    float acc[2][8][4] = {};
    issue(0, 0);
    for (int ch = 0; ch < nch; ch++) {
        const int st = ch & 1;
        if (ch + 1 < nch) { issue(ch + 1, st ^ 1); asm volatile("cp.async.wait_group 1;"); }
        else              { asm volatile("cp.async.wait_group 0;"); }
        __syncthreads();
        const uint32_t sAb = smb + (uint32_t)st * 18944;
        const uint32_t sBb = sAb + 8704;
        #pragma unroll
        for (int ks = 0; ks < 2; ks++) {
            uint32_t a[2][4];
            #pragma unroll
            for (int fm = 0; fm < 2; fm++) {
                uint32_t ad = sAb
                    + (uint32_t)(ks * 16 + ((lane >> 4) << 3) + (lane & 7)) * 272
                    + (uint32_t)(wm * 32 + fm * 16 + ((lane >> 3) & 1) * 8) * 2;
                ldsm4t(a[fm][0], a[fm][1], a[fm][2], a[fm][3], ad);
            }
            const uint32_t colb = (uint32_t)(ks * 16 + (lane >> 4) * 8) * 2;
            uint32_t bb[4][4];
            #pragma unroll
            for (int fn = 0; fn < 4; fn++) {
                uint32_t bd = sBb + (uint32_t)(wn * 64 + fn * 16 + (lane & 15)) * 80 + colb;
                ldsm4(bb[fn][0], bb[fn][1], bb[fn][2], bb[fn][3], bd);
            }
            #pragma unroll
            for (int fm = 0; fm < 2; fm++)
                #pragma unroll
                for (int fn = 0; fn < 4; fn++) {
                    mma_bf16(acc[fm][fn * 2],     a[fm], bb[fn][0], bb[fn][2]);
                    mma_bf16(acc[fm][fn * 2 + 1], a[fm], bb[fn][1], bb[fn][3]);
                }
        }
        __syncthreads();
    }

    const int fr = lane >> 2;
    const int fc = (lane & 3) * 2;
    #pragma unroll
    for (int fm = 0; fm < 2; fm++) {
        const int row0 = bm + wm * 32 + fm * 16 + fr;
        float s0 = 1.0f / scale[(size_t)b * mpb + row0];
        float s1 = 1.0f / scale[(size_t)b * mpb + row0 + 8];
        float* Cb = C + (size_t)b * c_bs;
        #pragma unroll
        for (int fn = 0; fn < 8; fn++) {
            const int col = bn + wn * 64 + fn * 8 + fc;
            float2 v0, v1;
            v0.x = acc[fm][fn][0] * s0; v0.y = acc[fm][fn][1] * s0;
            v1.x = acc[fm][fn][2] * s1; v1.y = acc[fm][fn][3] * s1;
            *(float2*)(Cb + (size_t)row0 * ldc + col) = v0;
            *(float2*)(Cb + (size_t)(row0 + 8) * ldc + col) = v1;
        }
    }
}

// ---------------------------------------------------------------------------
// Elementwise / transform kernels
// ---------------------------------------------------------------------------
__global__ void split_kernel(const float* __restrict__ in, bf16* __restrict__ hi,
                             bf16* __restrict__ lo, size_t n4) {
    size_t i = (size_t)blockIdx.x * 256 + threadIdx.x;
    if (i >= n4) return;
    float4 v = ((const float4*)in)[i];
    float vv[4] = {v.x, v.y, v.z, v.w};
    bf16 h[4];
    union { __nv_bfloat162 b2[2]; uint2 u; } uh, ul;
    #pragma unroll
    for (int j = 0; j < 4; j++) h[j] = __float2bfloat16(vv[j]);
    uh.b2[0].x = h[0]; uh.b2[0].y = h[1]; uh.b2[1].x = h[2]; uh.b2[1].y = h[3];
    ul.b2[0].x = __float2bfloat16(vv[0] - __bfloat162float(h[0]));
    ul.b2[0].y = __float2bfloat16(vv[1] - __bfloat162float(h[1]));
    ul.b2[1].x = __float2bfloat16(vv[2] - __bfloat162float(h[2]));
    ul.b2[1].y = __float2bfloat16(vv[3] - __bfloat162float(h[3]));
    ((uint2*)hi)[i] = uh.u;
    ((uint2*)lo)[i] = ul.u;
}

// transpose + split; if scaled, multiply input row p by er[p]=exp(rowmax-Mb)
__global__ void transpose_split_kernel(const float* __restrict__ in, bf16* __restrict__ ohi,
                                       bf16* __restrict__ olo, int R, int C,
                                       size_t ibs, size_t obs, int scaled) {
    __shared__ float tile[32][33];
    const int bz = blockIdx.z;
    const float* ip = in + (size_t)bz * ibs;
    int c0 = blockIdx.x * 32, r0 = blockIdx.y * 32;
    int tx = threadIdx.x, ty = threadIdx.y;
    #pragma unroll
    for (int i = ty; i < 32; i += 8)
        tile[i][tx] = ip[(size_t)(r0 + i) * C + c0 + tx];
    __syncthreads();
    float er = 1.f;
    if (scaled) er = __expf(g_rowmax[(size_t)bz * LL + r0 + tx] - g_Mb[bz]);
    size_t ob = (size_t)bz * obs;
    #pragma unroll
    for (int i = ty; i < 32; i += 8) {
        float v = tile[tx][i] * er;
        bf16 h = __float2bfloat16(v);
        size_t o = ob + (size_t)(c0 + i) * R + r0 + tx;
        ohi[o] = h;
        olo[o] = __float2bfloat16(v - __bfloat162float(h));
    }
}

__global__ void initstats_kernel() {
    int i = blockIdx.x * 256 + threadIdx.x;
    if (i < NB * LL) { g_rowmax[i] = -INFINITY; g_colsum[i] = 0.f; }
}

__global__ void mbmax_kernel() {
    const int b = blockIdx.x, t = threadIdx.x;
    float4 v = ((const float4*)(g_rowmax + (size_t)b * LL))[t];
    float m = fmaxf(fmaxf(v.x, v.y), fmaxf(v.z, v.w));
    #pragma unroll
    for (int o = 16; o; o >>= 1) m = fmaxf(m, __shfl_xor_sync(~0u, m, o));
    __shared__ float red[8];
    if ((t & 31) == 0) red[t >> 5] = m;
    __syncthreads();
    if (t == 0) {
        float M = red[0];
        #pragma unroll
        for (int i = 1; i < 8; i++) M = fmaxf(M, red[i]);
        g_Mb[b] = M;
    }
}

// Single fused pass over E: Tr = split(exp(E-rowmax)), rowsum direct,
// csum'[q] += er[p]*tr[p,q] via atomics.
__global__ __launch_bounds__(256) void dual_exp_kernel() {
    const int b = blockIdx.y;
    const int r0 = blockIdx.x * 64;
    const int w = threadIdx.x >> 5, lane = threadIdx.x & 31;
    const float Mb = g_Mb[b];
    const float* Eb = g_E + (size_t)b * LL * LL;
    bf16* Th = g_Tr_hi + (size_t)b * LL * LL;
    bf16* Tl = g_Tr_lo + (size_t)b * LL * LL;
    float cs[32];
    #pragma unroll
    for (int k = 0; k < 32; k++) cs[k] = 0.f;
    #pragma unroll 1
    for (int j = 0; j < 8; j++) {
        const int row = r0 + w * 8 + j;
        const float rm = g_rowmax[(size_t)b * LL + row];
        const float er = __expf(rm - Mb);
        const float4* src = (const float4*)(Eb + (size_t)row * LL);
        float s = 0.f;
        #pragma unroll
        for (int k = 0; k < 8; k++) {
            float4 v = src[lane + 32 * k];
            float t0 = __expf(v.x - rm), t1 = __expf(v.y - rm);
            float t2 = __expf(v.z - rm), t3 = __expf(v.w - rm);
            s += (t0 + t1) + (t2 + t3);
            cs[k * 4 + 0] += er * t0; cs[k * 4 + 1] += er * t1;
            cs[k * 4 + 2] += er * t2; cs[k * 4 + 3] += er * t3;
            bf16 h0 = __float2bfloat16(t0), h1 = __float2bfloat16(t1);
            bf16 h2 = __float2bfloat16(t2), h3 = __float2bfloat16(t3);
            union { __nv_bfloat162 b2[2]; uint2 u; } uh, ul;
            uh.b2[0].x = h0; uh.b2[0].y = h1; uh.b2[1].x = h2; uh.b2[1].y = h3;
            ul.b2[0].x = __float2bfloat16(t0 - __bfloat162float(h0));
            ul.b2[0].y = __float2bfloat16(t1 - __bfloat162float(h1));
            ul.b2[1].x = __float2bfloat16(t2 - __bfloat162float(h2));
            ul.b2[1].y = __float2bfloat16(t3 - __bfloat162float(h3));
            size_t o = (size_t)row * LL + 4 * (lane + 32 * k);
            *(uint2*)(Th + o) = uh.u;
            *(uint2*)(Tl + o) = ul.u;
        }
        #pragma unroll
        for (int o = 16; o; o >>= 1) s += __shfl_xor_sync(~0u, s, o);
        if (lane == 0) g_rowsum[(size_t)b * LL + row] = s;
    }
    #pragma unroll
    for (int k = 0; k < 8; k++)
        #pragma unroll
        for (int j2 = 0; j2 < 4; j2++)
            atomicAdd(g_colsum + (size_t)b * LL + 4 * (lane + 32 * k) + j2, cs[k * 4 + j2]);
}

// ---------------------------------------------------------------------------
#define SYM(p, s) do { void* _t; cudaGetSymbolAddress(&_t, s); p = decltype(p)(_t); } while (0)

extern "C" void kernel_launch(void* const* d_in, const int* in_sizes, int n_in,
                              void* d_out, int out_size) {
    const float* P   = (const float*)d_in[0];
    const float* Hyp = (const float*)d_in[1];
    const float* W   = (const float*)d_in[2];
    float* out = (float*)d_out;

    bf16 *Xph, *Xpl, *Xhh, *Xhl, *Wth, *Wtl, *Fph, *Fpl, *Fhh, *Fhl;
    bf16 *Hth, *Htl, *Pth, *Ptl, *Trh, *Trl;
    float *E, *rmax, *rsum, *csum;
    SYM(Xph, g_Xp_hi); SYM(Xpl, g_Xp_lo); SYM(Xhh, g_Xh_hi); SYM(Xhl, g_Xh_lo);
    SYM(Wth, g_Wt_hi); SYM(Wtl, g_Wt_lo);
    SYM(Fph, g_Fp_hi); SYM(Fpl, g_Fp_lo); SYM(Fhh, g_Fh_hi); SYM(Fhl, g_Fh_lo);
    SYM(Hth, g_Ht_hi); SYM(Htl, g_Ht_lo); SYM(Pth, g_Pt_hi); SYM(Ptl, g_Pt_lo);
    SYM(Trh, g_Tr_hi); SYM(Trl, g_Tr_lo);
    SYM(E, g_E);
    SYM(rmax, g_rowmax); SYM(rsum, g_rowsum); SYM(csum, g_colsum);

    dim3 t256(256), t32x8(32, 8);

    // input conversions
    split_kernel<<<8192, t256>>>(P, Xph, Xpl, NXD / 4);
    split_kernel<<<8192, t256>>>(Hyp, Xhh, Xhl, NXD / 4);
    transpose_split_kernel<<<dim3(8, 8, 1), t32x8>>>(W, Wth, Wtl, DD, HH, 0, 0, 0);
    transpose_split_kernel<<<dim3(8, 32, NB), t32x8>>>(Hyp, Hth, Htl, LL, DD,
                                                       (size_t)LL * DD, (size_t)LL * DD, 0);

    // proj: F = tanh(X @ W)
    gemm_split<<<dim3(256, 2, 1), t256>>>(Xph, Xpl, 0, DD, Wth, Wtl, 0, DD, DD, 1,
                                          nullptr, 0, HH, nullptr, 0, Fph, Fpl, nullptr);
    gemm_split<<<dim3(256, 2, 1), t256>>>(Xhh, Xhl, 0, DD, Wth, Wtl, 0, DD, DD, 1,
                                          nullptr, 0, HH, nullptr, 0, Fhh, Fhl, nullptr);

    // stats init + eij (E + rowmax atomics fused)
    initstats_kernel<<<128, t256>>>();
    gemm_split<<<dim3(8, 8, NB), t256>>>(Fph, Fpl, (size_t)LL * DD, HH,
                                         Fhh, Fhl, (size_t)LL * DD, HH, HH, 0,
                                         E, (size_t)LL * LL, LL, nullptr, LL,
                                         nullptr, nullptr, rmax);
    mbmax_kernel<<<NB, t256>>>();

    // fused exp/split/rowsum/colsum' pass (single read of E)
    dual_exp_kernel<<<dim3(16, NB), t256>>>();

    // Pt' = transpose(er[p] * P[p,d])
    transpose_split_kernel<<<dim3(8, 32, NB), t32x8>>>(P, Pth, Ptl, LL, DD,
                                                       (size_t)LL * DD, (size_t)LL * DD, 1);

    // betas = (Tr @ Ht) / rowsum
    gemm_split<<<dim3(8, 2, NB), t256>>>(Trh, Trl, (size_t)LL * LL, LL,
                                         Hth, Htl, (size_t)DD * LL, LL, LL, 2,
                                         out, (size_t)LL * DD, DD, rsum, LL,
                                         nullptr, nullptr, nullptr);
    // alphas = (Tr^T @ Pt') / csum'
    gemm_splitT<<<dim3(8, 2, NB), t256>>>(Trh, Trl, (size_t)LL * LL, LL,
                                          Pth, Ptl, (size_t)DD * LL, LL, LL,
                                          out + (size_t)NB * LL * DD, (size_t)LL * DD, DD,
                                          csum, LL);
}

// round 12
// speedup vs baseline: 1.0017x; 1.0017x over previous
#include <cuda_runtime.h>
#include <cuda_bf16.h>
#include <math.h>
#include <stdint.h>

#define NB 32
#define LL 1024
#define DD 256
#define HH 256
typedef __nv_bfloat16 bf16;

#define NXD ((size_t)NB * LL * DD)
#define NE  ((size_t)NB * LL * LL)

// ---------------------------------------------------------------------------
// Device scratch
// ---------------------------------------------------------------------------
__device__ __align__(256) bf16 g_Xp_hi[NXD], g_Xp_lo[NXD];
__device__ __align__(256) bf16 g_Xh_hi[NXD], g_Xh_lo[NXD];
__device__ __align__(256) bf16 g_Wt_hi[DD * HH], g_Wt_lo[DD * HH];
__device__ __align__(256) bf16 g_Fp_hi[NXD], g_Fp_lo[NXD];
__device__ __align__(256) bf16 g_Fh_hi[NXD], g_Fh_lo[NXD];
__device__ __align__(256) bf16 g_Ht_hi[NXD], g_Ht_lo[NXD];
__device__ __align__(256) bf16 g_Pt_hi[NXD], g_Pt_lo[NXD];
__device__ __align__(256) float g_E[NE];
__device__ __align__(256) bf16 g_Tr_hi[NE], g_Tr_lo[NE];
__device__ __align__(256) float g_rowmax[NB * LL], g_rowsum[NB * LL], g_colsum[NB * LL];
__device__ __align__(256) float g_Mb[NB];

// ---------------------------------------------------------------------------
// helpers
// ---------------------------------------------------------------------------
__device__ __forceinline__ uint32_t smem_u32(const void* p) {
    uint32_t a;
    asm("{ .reg .u64 t; cvta.to.shared.u64 t, %1; cvt.u32.u64 %0, t; }" : "=r"(a) : "l"(p));
    return a;
}
__device__ __forceinline__ void cp_async16(uint32_t dst, const void* src) {
    asm volatile("cp.async.cg.shared.global [%0], [%1], 16;" :: "r"(dst), "l"(src));
}
__device__ __forceinline__ void ldsm4(uint32_t& r0, uint32_t& r1, uint32_t& r2,
                                      uint32_t& r3, uint32_t addr) {
    asm volatile("ldmatrix.sync.aligned.m8n8.x4.shared.b16 {%0,%1,%2,%3}, [%4];"
                 : "=r"(r0), "=r"(r1), "=r"(r2), "=r"(r3) : "r"(addr));
}
__device__ __forceinline__ void ldsm4t(uint32_t& r0, uint32_t& r1, uint32_t& r2,
                                       uint32_t& r3, uint32_t addr) {
    asm volatile("ldmatrix.sync.aligned.m8n8.x4.trans.shared.b16 {%0,%1,%2,%3}, [%4];"
                 : "=r"(r0), "=r"(r1), "=r"(r2), "=r"(r3) : "r"(addr));
}
__device__ __forceinline__ void mma_bf16(float* c, const uint32_t* a, uint32_t b0, uint32_t b1) {
    asm volatile(
        "mma.sync.aligned.m16n8k16.row.col.f32.bf16.bf16.f32 "
        "{%0,%1,%2,%3}, {%4,%5,%6,%7}, {%8,%9}, {%0,%1,%2,%3};"
        : "+f"(c[0]), "+f"(c[1]), "+f"(c[2]), "+f"(c[3])
        : "r"(a[0]), "r"(a[1]), "r"(a[2]), "r"(a[3]), "r"(b0), "r"(b1));
}
__device__ __forceinline__ void atomicMaxF(float* a, float v) {
    if (v >= 0.f) atomicMax((int*)a, __float_as_int(v));
    else          atomicMin((unsigned int*)a, __float_as_uint(v));
}

// ---------------------------------------------------------------------------
// Split-bf16 warp-MMA GEMM (normal A): C[m,n] = sum_k A[m,k]*B[n,k]
// 3 passes (hh, h*Blo, Alo*h) in register acc. CTA 128x128, BK=32, cp.async
// double-buffered. epi: 0 fp32 C (+opt rowmax atomics); 1 tanh->split bf16;
// 2 scale 1/scale[b*mpb+m].
// ---------------------------------------------------------------------------
__global__ __launch_bounds__(256) void gemm_split(
    const bf16* __restrict__ Ahi, const bf16* __restrict__ Alo, size_t a_bs, int lda,
    const bf16* __restrict__ Bhi, const bf16* __restrict__ Blo, size_t b_bs, int ldb,
    int K, int epi,
    float* __restrict__ C, size_t c_bs, int ldc,
    const float* __restrict__ scale, int mpb,
    bf16* __restrict__ Fhi, bf16* __restrict__ Flo,
    float* __restrict__ rmaxAt)
{
    __shared__ __align__(16) uint8_t sm[2 * 20480];   // [stage][A 10240 | B 10240]
    const uint32_t smb = smem_u32(sm);
    const int tid = threadIdx.x, lane = tid & 31, wid = tid >> 5;
    const int wm = wid & 3, wn = wid >> 2;
    const int bm = blockIdx.x * 128, bn = blockIdx.y * 128, b = blockIdx.z;
    const int nk = K >> 5, nch = 3 * nk;

    const int r0s = tid >> 2,          kv0 = (tid & 3) * 8;
    const int r1s = (tid + 256) >> 2,  kv1 = ((tid + 256) & 3) * 8;

    auto issue = [&](int ch, int st) {
        const int pass = ch / nk;
        const int k0 = (ch - pass * nk) << 5;
        const bf16* Ap = (pass == 2 ? Alo : Ahi) + (size_t)b * a_bs;
        const bf16* Bp = (pass == 1 ? Blo : Bhi) + (size_t)b * b_bs;
        uint32_t da = smb + (uint32_t)st * 20480;
        uint32_t db = da + 10240;
        cp_async16(da + r0s * 80 + kv0 * 2, Ap + (size_t)(bm + r0s) * lda + k0 + kv0);
        cp_async16(da + r1s * 80 + kv1 * 2, Ap + (size_t)(bm + r1s) * lda + k0 + kv1);
        cp_async16(db + r0s * 80 + kv0 * 2, Bp + (size_t)(bn + r0s) * ldb + k0 + kv0);
        cp_async16(db + r1s * 80 + kv1 * 2, Bp + (size_t)(bn + r1s) * ldb + k0 + kv1);
        asm volatile("cp.async.commit_group;");
    };

    float acc[2][8][4] = {};
    issue(0, 0);
    for (int ch = 0; ch < nch; ch++) {
        const int st = ch & 1;
        if (ch + 1 < nch) { issue(ch + 1, st ^ 1); asm volatile("cp.async.wait_group 1;"); }
        else              { asm volatile("cp.async.wait_group 0;"); }
        __syncthreads();
        const uint32_t sAb = smb + (uint32_t)st * 20480;
        const uint32_t sBb = sAb + 10240;
        #pragma unroll
        for (int ks = 0; ks < 2; ks++) {
            const uint32_t colb = (uint32_t)(ks * 16 + (lane >> 4) * 8) * 2;
            uint32_t a[2][4];
            #pragma unroll
            for (int fm = 0; fm < 2; fm++) {
                uint32_t ad = sAb + (uint32_t)(wm * 32 + fm * 16 + (lane & 15)) * 80 + colb;
                ldsm4(a[fm][0], a[fm][1], a[fm][2], a[fm][3], ad);
            }
            uint32_t bb[4][4];
            #pragma unroll
            for (int fn = 0; fn < 4; fn++) {
                uint32_t bd = sBb + (uint32_t)(wn * 64 + fn * 16 + (lane & 15)) * 80 + colb;
                ldsm4(bb[fn][0], bb[fn][1], bb[fn][2], bb[fn][3], bd);
            }
            #pragma unroll
            for (int fm = 0; fm < 2; fm++)
                #pragma unroll
                for (int fn = 0; fn < 4; fn++) {
                    mma_bf16(acc[fm][fn * 2],     a[fm], bb[fn][0], bb[fn][2]);
                    mma_bf16(acc[fm][fn * 2 + 1], a[fm], bb[fn][1], bb[fn][3]);
                }
        }
        __syncthreads();
    }

    const int fr = lane >> 2;
    const int fc = (lane & 3) * 2;
    if (rmaxAt) {
        #pragma unroll
        for (int fm = 0; fm < 2; fm++)
            #pragma unroll
            for (int half = 0; half < 2; half++) {
                float m = -INFINITY;
                #pragma unroll
                for (int fn = 0; fn < 8; fn++) {
                    m = fmaxf(m, acc[fm][fn][half * 2]);
                    m = fmaxf(m, acc[fm][fn][half * 2 + 1]);
                }
                m = fmaxf(m, __shfl_xor_sync(~0u, m, 1));
                m = fmaxf(m, __shfl_xor_sync(~0u, m, 2));
                if ((lane & 3) == 0)
                    atomicMaxF(rmaxAt + (size_t)b * mpb + bm + wm * 32 + fm * 16 + fr + half * 8, m);
            }
    }
    #pragma unroll
    for (int fm = 0; fm < 2; fm++) {
        const int row0 = bm + wm * 32 + fm * 16 + fr;
        if (epi == 1) {
            #pragma unroll
            for (int half = 0; half < 2; half++) {
                const size_t gr = (size_t)(row0 + half * 8);
                #pragma unroll
                for (int fn = 0; fn < 8; fn++) {
                    const int col = bn + wn * 64 + fn * 8 + fc;
                    float v0 = tanhf(acc[fm][fn][half * 2]);
                    float v1 = tanhf(acc[fm][fn][half * 2 + 1]);
                    bf16 h0 = __float2bfloat16(v0), h1 = __float2bfloat16(v1);
                    __nv_bfloat162 hp, lp;
                    hp.x = h0; hp.y = h1;
                    lp.x = __float2bfloat16(v0 - __bfloat162float(h0));
                    lp.y = __float2bfloat16(v1 - __bfloat162float(h1));
                    size_t o = gr * ldc + col;
                    *(__nv_bfloat162*)(Fhi + o) = hp;
                    *(__nv_bfloat162*)(Flo + o) = lp;
                }
            }
        } else {
            float s0 = 1.f, s1 = 1.f;
            if (epi == 2) {
                s0 = 1.0f / scale[(size_t)b * mpb + row0];
                s1 = 1.0f / scale[(size_t)b * mpb + row0 + 8];
            }
            float* Cb = C + (size_t)b * c_bs;
            #pragma unroll
            for (int fn = 0; fn < 8; fn++) {
                const int col = bn + wn * 64 + fn * 8 + fc;
                float2 v0, v1;
                v0.x = acc[fm][fn][0] * s0; v0.y = acc[fm][fn][1] * s0;
                v1.x = acc[fm][fn][2] * s1; v1.y = acc[fm][fn][3] * s1;
                *(float2*)(Cb + (size_t)row0 * ldc + col) = v0;
                *(float2*)(Cb + (size_t)(row0 + 8) * ldc + col) = v1;
            }
        }
    }
}

// ---------------------------------------------------------------------------
// Trans-A variant (alphas): C[m,n] = sum_k A[k,m]*B[n,k]  (A read transposed
// via ldmatrix.trans). A tile [32k x 128m] pitch 272B, B tile [128n x 32k]
// pitch 80B. Scaled fp32 output.
// ---------------------------------------------------------------------------
__global__ __launch_bounds__(256) void gemm_splitT(
    const bf16* __restrict__ Ahi, const bf16* __restrict__ Alo, size_t a_bs, int lda,
    const bf16* __restrict__ Bhi, const bf16* __restrict__ Blo, size_t b_bs, int ldb,
    int K,
    float* __restrict__ C, size_t c_bs, int ldc,
    const float* __restrict__ scale, int mpb)
{
    __shared__ __align__(16) uint8_t sm[2 * 18944];   // [stage][A 8704 | B 10240]
    const uint32_t smb = smem_u32(sm);
    const int tid = threadIdx.x, lane = tid & 31, wid = tid >> 5;
    const int wm = wid & 3, wn = wid >> 2;
    const int bm = blockIdx.x * 128, bn = blockIdx.y * 128, b = blockIdx.z;
    const int nk = K >> 5, nch = 3 * nk;

    // A: 32 k-rows x 128 m-cols = 512 chunks -> 2 per thread
    const int ar  = tid >> 4,          akv = (tid & 15) * 8;
    const int r0s = tid >> 2,          kv0 = (tid & 3) * 8;
    const int r1s = (tid + 256) >> 2,  kv1 = ((tid + 256) & 3) * 8;

    auto issue = [&](int ch, int st) {
        const int pass = ch / nk;
        const int k0 = (ch - pass * nk) << 5;
        const bf16* Ap = (pass == 2 ? Alo : Ahi) + (size_t)b * a_bs;
        const bf16* Bp = (pass == 1 ? Blo : Bhi) + (size_t)b * b_bs;
        uint32_t da = smb + (uint32_t)st * 18944;
        uint32_t db = da + 8704;
        cp_async16(da + ar * 272 + akv * 2,
                   Ap + (size_t)(k0 + ar) * lda + bm + akv);
        cp_async16(da + (ar + 16) * 272 + akv * 2,
                   Ap + (size_t)(k0 + ar + 16) * lda + bm + akv);
        cp_async16(db + r0s * 80 + kv0 * 2, Bp + (size_t)(bn + r0s) * ldb + k0 + kv0);
        cp_async16(db + r1s * 80 + kv1 * 2, Bp + (size_t)(bn + r1s) * ldb + k0 + kv1);
        asm volatile("cp.async.commit_group;");
    };

    float acc[2][8][4] = {};
    issue(0, 0);
    for (int ch = 0; ch < nch; ch++) {
        const int st = ch & 1;
        if (ch + 1 < nch) { issue(ch + 1, st ^ 1); asm volatile("cp.async.wait_group 1;"); }
        else              { asm volatile("cp.async.wait_group 0;"); }
        __syncthreads();
        const uint32_t sAb = smb + (uint32_t)st * 18944;
        const uint32_t sBb = sAb + 8704;
        #pragma unroll
        for (int ks = 0; ks < 2; ks++) {
            uint32_t a[2][4];
            #pragma unroll
            for (int fm = 0; fm < 2; fm++) {
                uint32_t ad = sAb
                    + (uint32_t)(ks * 16 + ((lane >> 4) << 3) + (lane & 7)) * 272
                    + (uint32_t)(wm * 32 + fm * 16 + ((lane >> 3) & 1) * 8) * 2;
                ldsm4t(a[fm][0], a[fm][1], a[fm][2], a[fm][3], ad);
            }
            const uint32_t colb = (uint32_t)(ks * 16 + (lane >> 4) * 8) * 2;
            uint32_t bb[4][4];
            #pragma unroll
            for (int fn = 0; fn < 4; fn++) {
                uint32_t bd = sBb + (uint32_t)(wn * 64 + fn * 16 + (lane & 15)) * 80 + colb;
                ldsm4(bb[fn][0], bb[fn][1], bb[fn][2], bb[fn][3], bd);
            }
            #pragma unroll
            for (int fm = 0; fm < 2; fm++)
                #pragma unroll
                for (int fn = 0; fn < 4; fn++) {
                    mma_bf16(acc[fm][fn * 2],     a[fm], bb[fn][0], bb[fn][2]);
                    mma_bf16(acc[fm][fn * 2 + 1], a[fm], bb[fn][1], bb[fn][3]);
                }
        }
        __syncthreads();
    }

    const int fr = lane >> 2;
    const int fc = (lane & 3) * 2;
    #pragma unroll
    for (int fm = 0; fm < 2; fm++) {
        const int row0 = bm + wm * 32 + fm * 16 + fr;
        float s0 = 1.0f / scale[(size_t)b * mpb + row0];
        float s1 = 1.0f / scale[(size_t)b * mpb + row0 + 8];
        float* Cb = C + (size_t)b * c_bs;
        #pragma unroll
        for (int fn = 0; fn < 8; fn++) {
            const int col = bn + wn * 64 + fn * 8 + fc;
            float2 v0, v1;
            v0.x = acc[fm][fn][0] * s0; v0.y = acc[fm][fn][1] * s0;
            v1.x = acc[fm][fn][2] * s1; v1.y = acc[fm][fn][3] * s1;
            *(float2*)(Cb + (size_t)row0 * ldc + col) = v0;
            *(float2*)(Cb + (size_t)(row0 + 8) * ldc + col) = v1;
        }
    }
}

// ---------------------------------------------------------------------------
// Elementwise / transform kernels
// ---------------------------------------------------------------------------
__global__ void split_kernel(const float* __restrict__ in, bf16* __restrict__ hi,
                             bf16* __restrict__ lo, size_t n4) {
    size_t i = (size_t)blockIdx.x * 256 + threadIdx.x;
    if (i >= n4) return;
    float4 v = ((const float4*)in)[i];
    float vv[4] = {v.x, v.y, v.z, v.w};
    bf16 h[4];
    union { __nv_bfloat162 b2[2]; uint2 u; } uh, ul;
    #pragma unroll
    for (int j = 0; j < 4; j++) h[j] = __float2bfloat16(vv[j]);
    uh.b2[0].x = h[0]; uh.b2[0].y = h[1]; uh.b2[1].x = h[2]; uh.b2[1].y = h[3];
    ul.b2[0].x = __float2bfloat16(vv[0] - __bfloat162float(h[0]));
    ul.b2[0].y = __float2bfloat16(vv[1] - __bfloat162float(h[1]));
    ul.b2[1].x = __float2bfloat16(vv[2] - __bfloat162float(h[2]));
    ul.b2[1].y = __float2bfloat16(vv[3] - __bfloat162float(h[3]));
    ((uint2*)hi)[i] = uh.u;
    ((uint2*)lo)[i] = ul.u;
}

// transpose + split; if scaled, multiply input row p by er[p]=exp(rowmax-Mb)
__global__ void transpose_split_kernel(const float* __restrict__ in, bf16* __restrict__ ohi,
                                       bf16* __restrict__ olo, int R, int C,
                                       size_t ibs, size_t obs, int scaled) {
    __shared__ float tile[32][33];
    const int bz = blockIdx.z;
    const float* ip = in + (size_t)bz * ibs;
    int c0 = blockIdx.x * 32, r0 = blockIdx.y * 32;
    int tx = threadIdx.x, ty = threadIdx.y;
    #pragma unroll
    for (int i = ty; i < 32; i += 8)
        tile[i][tx] = ip[(size_t)(r0 + i) * C + c0 + tx];
    __syncthreads();
    float er = 1.f;
    if (scaled) er = __expf(g_rowmax[(size_t)bz * LL + r0 + tx] - g_Mb[bz]);
    size_t ob = (size_t)bz * obs;
    #pragma unroll
    for (int i = ty; i < 32; i += 8) {
        float v = tile[tx][i] * er;
        bf16 h = __float2bfloat16(v);
        size_t o = ob + (size_t)(c0 + i) * R + r0 + tx;
        ohi[o] = h;
        olo[o] = __float2bfloat16(v - __bfloat162float(h));
    }
}

__global__ void initstats_kernel() {
    int i = blockIdx.x * 256 + threadIdx.x;
    if (i < NB * LL) { g_rowmax[i] = -INFINITY; g_colsum[i] = 0.f; }
}

__global__ void mbmax_kernel() {
    const int b = blockIdx.x, t = threadIdx.x;
    float4 v = ((const float4*)(g_rowmax + (size_t)b * LL))[t];
    float m = fmaxf(fmaxf(v.x, v.y), fmaxf(v.z, v.w));
    #pragma unroll
    for (int o = 16; o; o >>= 1) m = fmaxf(m, __shfl_xor_sync(~0u, m, o));
    __shared__ float red[8];
    if ((t & 31) == 0) red[t >> 5] = m;
    __syncthreads();
    if (t == 0) {
        float M = red[0];
        #pragma unroll
        for (int i = 1; i < 8; i++) M = fmaxf(M, red[i]);
        g_Mb[b] = M;
    }
}

// Single fused pass over E: Tr = split(exp(E-rowmax)), rowsum direct,
// csum'[q] += er[p]*tr[p,q] via atomics.
__global__ __launch_bounds__(256) void dual_exp_kernel() {
    const int b = blockIdx.y;
    const int r0 = blockIdx.x * 64;
    const int w = threadIdx.x >> 5, lane = threadIdx.x & 31;
    const float Mb = g_Mb[b];
    const float* Eb = g_E + (size_t)b * LL * LL;
    bf16* Th = g_Tr_hi + (size_t)b * LL * LL;
    bf16* Tl = g_Tr_lo + (size_t)b * LL * LL;
    float cs[32];
    #pragma unroll
    for (int k = 0; k < 32; k++) cs[k] = 0.f;
    #pragma unroll 1
    for (int j = 0; j < 8; j++) {
        const int row = r0 + w * 8 + j;
        const float rm = g_rowmax[(size_t)b * LL + row];
        const float er = __expf(rm - Mb);
        const float4* src = (const float4*)(Eb + (size_t)row * LL);
        float s = 0.f;
        #pragma unroll
        for (int k = 0; k < 8; k++) {
            float4 v = src[lane + 32 * k];
            float t0 = __expf(v.x - rm), t1 = __expf(v.y - rm);
            float t2 = __expf(v.z - rm), t3 = __expf(v.w - rm);
            s += (t0 + t1) + (t2 + t3);
            cs[k * 4 + 0] += er * t0; cs[k * 4 + 1] += er * t1;
            cs[k * 4 + 2] += er * t2; cs[k * 4 + 3] += er * t3;
            bf16 h0 = __float2bfloat16(t0), h1 = __float2bfloat16(t1);
            bf16 h2 = __float2bfloat16(t2), h3 = __float2bfloat16(t3);
            union { __nv_bfloat162 b2[2]; uint2 u; } uh, ul;
            uh.b2[0].x = h0; uh.b2[0].y = h1; uh.b2[1].x = h2; uh.b2[1].y = h3;
            ul.b2[0].x = __float2bfloat16(t0 - __bfloat162float(h0));
            ul.b2[0].y = __float2bfloat16(t1 - __bfloat162float(h1));
            ul.b2[1].x = __float2bfloat16(t2 - __bfloat162float(h2));
            ul.b2[1].y = __float2bfloat16(t3 - __bfloat162float(h3));
            size_t o = (size_t)row * LL + 4 * (lane + 32 * k);
            *(uint2*)(Th + o) = uh.u;
            *(uint2*)(Tl + o) = ul.u;
        }
        #pragma unroll
        for (int o = 16; o; o >>= 1) s += __shfl_xor_sync(~0u, s, o);
        if (lane == 0) g_rowsum[(size_t)b * LL + row] = s;
    }
    #pragma unroll
    for (int k = 0; k < 8; k++)
        #pragma unroll
        for (int j2 = 0; j2 < 4; j2++)
            atomicAdd(g_colsum + (size_t)b * LL + 4 * (lane + 32 * k) + j2, cs[k * 4 + j2]);
}

// ---------------------------------------------------------------------------
#define SYM(p, s) do { void* _t; cudaGetSymbolAddress(&_t, s); p = decltype(p)(_t); } while (0)

extern "C" void kernel_launch(void* const* d_in, const int* in_sizes, int n_in,
                              void* d_out, int out_size) {
    const float* P   = (const float*)d_in[0];
    const float* Hyp = (const float*)d_in[1];
    const float* W   = (const float*)d_in[2];
    float* out = (float*)d_out;

    bf16 *Xph, *Xpl, *Xhh, *Xhl, *Wth, *Wtl, *Fph, *Fpl, *Fhh, *Fhl;
    bf16 *Hth, *Htl, *Pth, *Ptl, *Trh, *Trl;
    float *E, *rmax, *rsum, *csum;
    SYM(Xph, g_Xp_hi); SYM(Xpl, g_Xp_lo); SYM(Xhh, g_Xh_hi); SYM(Xhl, g_Xh_lo);
    SYM(Wth, g_Wt_hi); SYM(Wtl, g_Wt_lo);
    SYM(Fph, g_Fp_hi); SYM(Fpl, g_Fp_lo); SYM(Fhh, g_Fh_hi); SYM(Fhl, g_Fh_lo);
    SYM(Hth, g_Ht_hi); SYM(Htl, g_Ht_lo); SYM(Pth, g_Pt_hi); SYM(Ptl, g_Pt_lo);
    SYM(Trh, g_Tr_hi); SYM(Trl, g_Tr_lo);
    SYM(E, g_E);
    SYM(rmax, g_rowmax); SYM(rsum, g_rowsum); SYM(csum, g_colsum);

    dim3 t256(256), t32x8(32, 8);

    // input conversions
    split_kernel<<<8192, t256>>>(P, Xph, Xpl, NXD / 4);
    split_kernel<<<8192, t256>>>(Hyp, Xhh, Xhl, NXD / 4);
    transpose_split_kernel<<<dim3(8, 8, 1), t32x8>>>(W, Wth, Wtl, DD, HH, 0, 0, 0);
    transpose_split_kernel<<<dim3(8, 32, NB), t32x8>>>(Hyp, Hth, Htl, LL, DD,
                                                       (size_t)LL * DD, (size_t)LL * DD, 0);

    // proj: F = tanh(X @ W)
    gemm_split<<<dim3(256, 2, 1), t256>>>(Xph, Xpl, 0, DD, Wth, Wtl, 0, DD, DD, 1,
                                          nullptr, 0, HH, nullptr, 0, Fph, Fpl, nullptr);
    gemm_split<<<dim3(256, 2, 1), t256>>>(Xhh, Xhl, 0, DD, Wth, Wtl, 0, DD, DD, 1,
                                          nullptr, 0, HH, nullptr, 0, Fhh, Fhl, nullptr);

    // stats init + eij (E + rowmax atomics fused)
    initstats_kernel<<<128, t256>>>();
    gemm_split<<<dim3(8, 8, NB), t256>>>(Fph, Fpl, (size_t)LL * DD, HH,
                                         Fhh, Fhl, (size_t)LL * DD, HH, HH, 0,
                                         E, (size_t)LL * LL, LL, nullptr, LL,
                                         nullptr, nullptr, rmax);
    mbmax_kernel<<<NB, t256>>>();

    // fused exp/split/rowsum/colsum' pass (single read of E)
    dual_exp_kernel<<<dim3(16, NB), t256>>>();

    // Pt' = transpose(er[p] * P[p,d])
    transpose_split_kernel<<<dim3(8, 32, NB), t32x8>>>(P, Pth, Ptl, LL, DD,
                                                       (size_t)LL * DD, (size_t)LL * DD, 1);

    // betas = (Tr @ Ht) / rowsum
    gemm_split<<<dim3(8, 2, NB), t256>>>(Trh, Trl, (size_t)LL * LL, LL,
                                         Hth, Htl, (size_t)DD * LL, LL, LL, 2,
                                         out, (size_t)LL * DD, DD, rsum, LL,
                                         nullptr, nullptr, nullptr);
    // alphas = (Tr^T @ Pt') / csum'
    gemm_splitT<<<dim3(8, 2, NB), t256>>>(Trh, Trl, (size_t)LL * LL, LL,
                                          Pth, Ptl, (size_t)DD * LL, LL, LL,
                                          out + (size_t)NB * LL * DD, (size_t)LL * DD, DD,
                                          csum, LL);
}

// round 13
// speedup vs baseline: 1.1233x; 1.1213x over previous
#include <cuda_runtime.h>
#include <cuda_bf16.h>
#include <math.h>
#include <stdint.h>

#define NB 32
#define LL 1024
#define DD 256
#define HH 256
typedef __nv_bfloat16 bf16;

#define NXD ((size_t)NB * LL * DD)
#define NE  ((size_t)NB * LL * LL)

// ---------------------------------------------------------------------------
// Device scratch
// ---------------------------------------------------------------------------
__device__ __align__(256) bf16 g_Xp_hi[NXD], g_Xp_lo[NXD];
__device__ __align__(256) bf16 g_Xh_hi[NXD], g_Xh_lo[NXD];
__device__ __align__(256) bf16 g_Wt_hi[DD * HH], g_Wt_lo[DD * HH];
__device__ __align__(256) bf16 g_Fp_hi[NXD], g_Fp_lo[NXD];
__device__ __align__(256) bf16 g_Fh_hi[NXD], g_Fh_lo[NXD];
__device__ __align__(256) bf16 g_Ht_hi[NXD], g_Ht_lo[NXD];
__device__ __align__(256) bf16 g_Pt_hi[NXD], g_Pt_lo[NXD];
__device__ __align__(256) float g_E[NE];
__device__ __align__(256) bf16 g_Tr_hi[NE], g_Tr_lo[NE];
__device__ __align__(256) float g_rowmax[NB * LL], g_rowsum[NB * LL], g_colsum[NB * LL];
__device__ __align__(256) float g_Mb[NB];

// ---------------------------------------------------------------------------
// helpers
// ---------------------------------------------------------------------------
__device__ __forceinline__ uint32_t smem_u32(const void* p) {
    uint32_t a;
    asm("{ .reg .u64 t; cvta.to.shared.u64 t, %1; cvt.u32.u64 %0, t; }" : "=r"(a) : "l"(p));
    return a;
}
__device__ __forceinline__ void cp_async16(uint32_t dst, const void* src) {
    asm volatile("cp.async.cg.shared.global [%0], [%1], 16;" :: "r"(dst), "l"(src));
}
__device__ __forceinline__ void ldsm4(uint32_t* r, uint32_t addr) {
    asm volatile("ldmatrix.sync.aligned.m8n8.x4.shared.b16 {%0,%1,%2,%3}, [%4];"
                 : "=r"(r[0]), "=r"(r[1]), "=r"(r[2]), "=r"(r[3]) : "r"(addr));
}
__device__ __forceinline__ void ldsm4t(uint32_t* r, uint32_t addr) {
    asm volatile("ldmatrix.sync.aligned.m8n8.x4.trans.shared.b16 {%0,%1,%2,%3}, [%4];"
                 : "=r"(r[0]), "=r"(r[1]), "=r"(r[2]), "=r"(r[3]) : "r"(addr));
}
__device__ __forceinline__ void mma_bf16(float* c, const uint32_t* a, uint32_t b0, uint32_t b1) {
    asm volatile(
        "mma.sync.aligned.m16n8k16.row.col.f32.bf16.bf16.f32 "
        "{%0,%1,%2,%3}, {%4,%5,%6,%7}, {%8,%9}, {%0,%1,%2,%3};"
        : "+f"(c[0]), "+f"(c[1]), "+f"(c[2]), "+f"(c[3])
        : "r"(a[0]), "r"(a[1]), "r"(a[2]), "r"(a[3]), "r"(b0), "r"(b1));
}
__device__ __forceinline__ void atomicMaxF(float* a, float v) {
    if (v >= 0.f) atomicMax((int*)a, __float_as_int(v));
    else          atomicMin((unsigned int*)a, __float_as_uint(v));
}

// stage layout (gemm_split): Ahi 10240 | Alo 10240 | Bhi 10240 | Blo 10240
#define STG  40960
// stage layout (gemm_splitT): Ahi 8704 | Alo 8704 | Bhi 10240 | Blo 10240
#define STGT 37888

// ---------------------------------------------------------------------------
// Fused split-bf16 warp-MMA GEMM: C[m,n] = sum_k A[m,k]*B[n,k]
// All 3 products (hh, lo*hi, hi*lo) accumulated in ONE K-sweep per chunk.
// CTA 128x128, BK=32, cp.async double-buffered, dynamic smem 2*40960.
// epi: 0 fp32 C (+opt rowmax atomics); 1 tanh->split bf16; 2 scale 1/scale.
// ---------------------------------------------------------------------------
__global__ __launch_bounds__(256, 2) void gemm_split(
    const bf16* __restrict__ Ahi, const bf16* __restrict__ Alo, size_t a_bs, int lda,
    const bf16* __restrict__ Bhi, const bf16* __restrict__ Blo, size_t b_bs, int ldb,
    int K, int epi,
    float* __restrict__ C, size_t c_bs, int ldc,
    const float* __restrict__ scale, int mpb,
    bf16* __restrict__ Fhi, bf16* __restrict__ Flo,
    float* __restrict__ rmaxAt)
{
    extern __shared__ __align__(16) uint8_t sm[];
    const uint32_t smb = smem_u32(sm);
    const int tid = threadIdx.x, lane = tid & 31, wid = tid >> 5;
    const int wm = wid & 3, wn = wid >> 2;
    const int bm = blockIdx.x * 128, bn = blockIdx.y * 128, b = blockIdx.z;
    const int nch = K >> 5;

    const int r0s = tid >> 2,  kv0 = (tid & 3) * 8;
    const int r1s = r0s + 64;

    const bf16* Ah = Ahi + (size_t)b * a_bs;
    const bf16* Al = Alo + (size_t)b * a_bs;
    const bf16* Bh = Bhi + (size_t)b * b_bs;
    const bf16* Bl = Blo + (size_t)b * b_bs;

    auto issue = [&](int ch, int st) {
        const int k0 = ch << 5;
        uint32_t s0 = smb + (uint32_t)st * STG;
        const size_t oa0 = (size_t)(bm + r0s) * lda + k0 + kv0;
        const size_t oa1 = (size_t)(bm + r1s) * lda + k0 + kv0;
        const size_t ob0 = (size_t)(bn + r0s) * ldb + k0 + kv0;
        const size_t ob1 = (size_t)(bn + r1s) * ldb + k0 + kv0;
        cp_async16(s0         + r0s * 80 + kv0 * 2, Ah + oa0);
        cp_async16(s0         + r1s * 80 + kv0 * 2, Ah + oa1);
        cp_async16(s0 + 10240 + r0s * 80 + kv0 * 2, Al + oa0);
        cp_async16(s0 + 10240 + r1s * 80 + kv0 * 2, Al + oa1);
        cp_async16(s0 + 20480 + r0s * 80 + kv0 * 2, Bh + ob0);
        cp_async16(s0 + 20480 + r1s * 80 + kv0 * 2, Bh + ob1);
        cp_async16(s0 + 30720 + r0s * 80 + kv0 * 2, Bl + ob0);
        cp_async16(s0 + 30720 + r1s * 80 + kv0 * 2, Bl + ob1);
        asm volatile("cp.async.commit_group;");
    };

    float acc[2][8][4] = {};
    issue(0, 0);
    for (int ch = 0; ch < nch; ch++) {
        const int st = ch & 1;
        if (ch + 1 < nch) { issue(ch + 1, st ^ 1); asm volatile("cp.async.wait_group 1;"); }
        else              { asm volatile("cp.async.wait_group 0;"); }
        __syncthreads();
        const uint32_t s0 = smb + (uint32_t)st * STG;
        #pragma unroll
        for (int ks = 0; ks < 2; ks++) {
            const uint32_t colb = (uint32_t)(ks * 16 + (lane >> 4) * 8) * 2;
            const uint32_t arow = (uint32_t)(wm * 32 + (lane & 15)) * 80 + colb;
            const uint32_t brow = (uint32_t)(wn * 64 + (lane & 15)) * 80 + colb;
            uint32_t ah[2][4];
            ldsm4(ah[0], s0 + arow);
            ldsm4(ah[1], s0 + arow + 16 * 80);
            uint32_t bh[4][4];
            #pragma unroll
            for (int fn = 0; fn < 4; fn++)
                ldsm4(bh[fn], s0 + 20480 + brow + fn * 16 * 80);
            #pragma unroll
            for (int fm = 0; fm < 2; fm++)
                #pragma unroll
                for (int fn = 0; fn < 4; fn++) {
                    mma_bf16(acc[fm][fn * 2],     ah[fm], bh[fn][0], bh[fn][2]);
                    mma_bf16(acc[fm][fn * 2 + 1], ah[fm], bh[fn][1], bh[fn][3]);
                }
            uint32_t al[2][4];
            ldsm4(al[0], s0 + 10240 + arow);
            ldsm4(al[1], s0 + 10240 + arow + 16 * 80);
            #pragma unroll
            for (int fm = 0; fm < 2; fm++)
                #pragma unroll
                for (int fn = 0; fn < 4; fn++) {
                    mma_bf16(acc[fm][fn * 2],     al[fm], bh[fn][0], bh[fn][2]);
                    mma_bf16(acc[fm][fn * 2 + 1], al[fm], bh[fn][1], bh[fn][3]);
                }
            uint32_t bl[4][4];
            #pragma unroll
            for (int fn = 0; fn < 4; fn++)
                ldsm4(bl[fn], s0 + 30720 + brow + fn * 16 * 80);
            #pragma unroll
            for (int fm = 0; fm < 2; fm++)
                #pragma unroll
                for (int fn = 0; fn < 4; fn++) {
                    mma_bf16(acc[fm][fn * 2],     ah[fm], bl[fn][0], bl[fn][2]);
                    mma_bf16(acc[fm][fn * 2 + 1], ah[fm], bl[fn][1], bl[fn][3]);
                }
        }
        __syncthreads();
    }

    const int fr = lane >> 2;
    const int fc = (lane & 3) * 2;
    if (rmaxAt) {
        #pragma unroll
        for (int fm = 0; fm < 2; fm++)
            #pragma unroll
            for (int half = 0; half < 2; half++) {
                float m = -INFINITY;
                #pragma unroll
                for (int fn = 0; fn < 8; fn++) {
                    m = fmaxf(m, acc[fm][fn][half * 2]);
                    m = fmaxf(m, acc[fm][fn][half * 2 + 1]);
                }
                m = fmaxf(m, __shfl_xor_sync(~0u, m, 1));
                m = fmaxf(m, __shfl_xor_sync(~0u, m, 2));
                if ((lane & 3) == 0)
                    atomicMaxF(rmaxAt + (size_t)b * mpb + bm + wm * 32 + fm * 16 + fr + half * 8, m);
            }
    }
    #pragma unroll
    for (int fm = 0; fm < 2; fm++) {
        const int row0 = bm + wm * 32 + fm * 16 + fr;
        if (epi == 1) {
            #pragma unroll
            for (int half = 0; half < 2; half++) {
                const size_t gr = (size_t)(row0 + half * 8);
                #pragma unroll
                for (int fn = 0; fn < 8; fn++) {
                    const int col = bn + wn * 64 + fn * 8 + fc;
                    float v0 = tanhf(acc[fm][fn][half * 2]);
                    float v1 = tanhf(acc[fm][fn][half * 2 + 1]);
                    bf16 h0 = __float2bfloat16(v0), h1 = __float2bfloat16(v1);
                    __nv_bfloat162 hp, lp;
                    hp.x = h0; hp.y = h1;
                    lp.x = __float2bfloat16(v0 - __bfloat162float(h0));
                    lp.y = __float2bfloat16(v1 - __bfloat162float(h1));
                    size_t o = gr * ldc + col;
                    *(__nv_bfloat162*)(Fhi + o) = hp;
                    *(__nv_bfloat162*)(Flo + o) = lp;
                }
            }
        } else {
            float s0 = 1.f, s1 = 1.f;
            if (epi == 2) {
                s0 = 1.0f / scale[(size_t)b * mpb + row0];
                s1 = 1.0f / scale[(size_t)b * mpb + row0 + 8];
            }
            float* Cb = C + (size_t)b * c_bs;
            #pragma unroll
            for (int fn = 0; fn < 8; fn++) {
                const int col = bn + wn * 64 + fn * 8 + fc;
                float2 v0, v1;
                v0.x = acc[fm][fn][0] * s0; v0.y = acc[fm][fn][1] * s0;
                v1.x = acc[fm][fn][2] * s1; v1.y = acc[fm][fn][3] * s1;
                *(float2*)(Cb + (size_t)row0 * ldc + col) = v0;
                *(float2*)(Cb + (size_t)(row0 + 8) * ldc + col) = v1;
            }
        }
    }
}

// ---------------------------------------------------------------------------
// Fused trans-A variant (alphas): C[m,n] = sum_k A[k,m]*B[n,k]
// A read transposed via ldmatrix.trans; single K-sweep with all 3 passes.
// Dynamic smem 2*37888. Scaled fp32 output.
// ---------------------------------------------------------------------------
__global__ __launch_bounds__(256, 2) void gemm_splitT(
    const bf16* __restrict__ Ahi, const bf16* __restrict__ Alo, size_t a_bs, int lda,
    const bf16* __restrict__ Bhi, const bf16* __restrict__ Blo, size_t b_bs, int ldb,
    int K,
    float* __restrict__ C, size_t c_bs, int ldc,
    const float* __restrict__ scale, int mpb)
{
    extern __shared__ __align__(16) uint8_t sm[];
    const uint32_t smb = smem_u32(sm);
    const int tid = threadIdx.x, lane = tid & 31, wid = tid >> 5;
    const int wm = wid & 3, wn = wid >> 2;
    const int bm = blockIdx.x * 128, bn = blockIdx.y * 128, b = blockIdx.z;
    const int nch = K >> 5;

    const int ar  = tid >> 4,  akv = (tid & 15) * 8;
    const int r0s = tid >> 2,  kv0 = (tid & 3) * 8;
    const int r1s = r0s + 64;

    const bf16* Ah = Ahi + (size_t)b * a_bs;
    const bf16* Al = Alo + (size_t)b * a_bs;
    const bf16* Bh = Bhi + (size_t)b * b_bs;
    const bf16* Bl = Blo + (size_t)b * b_bs;

    auto issue = [&](int ch, int st) {
        const int k0 = ch << 5;
        uint32_t s0 = smb + (uint32_t)st * STGT;
        const size_t oa0 = (size_t)(k0 + ar) * lda + bm + akv;
        const size_t oa1 = (size_t)(k0 + ar + 16) * lda + bm + akv;
        const size_t ob0 = (size_t)(bn + r0s) * ldb + k0 + kv0;
        const size_t ob1 = (size_t)(bn + r1s) * ldb + k0 + kv0;
        cp_async16(s0         + ar * 272 + akv * 2,        Ah + oa0);
        cp_async16(s0         + (ar + 16) * 272 + akv * 2, Ah + oa1);
        cp_async16(s0 + 8704  + ar * 272 + akv * 2,        Al + oa0);
        cp_async16(s0 + 8704  + (ar + 16) * 272 + akv * 2, Al + oa1);
        cp_async16(s0 + 17408 + r0s * 80 + kv0 * 2, Bh + ob0);
        cp_async16(s0 + 17408 + r1s * 80 + kv0 * 2, Bh + ob1);
        cp_async16(s0 + 27648 + r0s * 80 + kv0 * 2, Bl + ob0);
        cp_async16(s0 + 27648 + r1s * 80 + kv0 * 2, Bl + ob1);
        asm volatile("cp.async.commit_group;");
    };

    float acc[2][8][4] = {};
    issue(0, 0);
    for (int ch = 0; ch < nch; ch++) {
        const int st = ch & 1;
        if (ch + 1 < nch) { issue(ch + 1, st ^ 1); asm volatile("cp.async.wait_group 1;"); }
        else              { asm volatile("cp.async.wait_group 0;"); }
        __syncthreads();
        const uint32_t s0 = smb + (uint32_t)st * STGT;
        #pragma unroll
        for (int ks = 0; ks < 2; ks++) {
            const uint32_t atrow = (uint32_t)(ks * 16 + ((lane >> 4) << 3) + (lane & 7)) * 272;
            const uint32_t acol0 = (uint32_t)(wm * 32 + ((lane >> 3) & 1) * 8) * 2;
            const uint32_t colb  = (uint32_t)(ks * 16 + (lane >> 4) * 8) * 2;
            const uint32_t brow  = (uint32_t)(wn * 64 + (lane & 15)) * 80 + colb;
            uint32_t ah[2][4];
            ldsm4t(ah[0], s0 + atrow + acol0);
            ldsm4t(ah[1], s0 + atrow + acol0 + 32);   // +16 cols * 2B
            uint32_t bh[4][4];
            #pragma unroll
            for (int fn = 0; fn < 4; fn++)
                ldsm4(bh[fn], s0 + 17408 + brow + fn * 16 * 80);
            #pragma unroll
            for (int fm = 0; fm < 2; fm++)
                #pragma unroll
                for (int fn = 0; fn < 4; fn++) {
                    mma_bf16(acc[fm][fn * 2],     ah[fm], bh[fn][0], bh[fn][2]);
                    mma_bf16(acc[fm][fn * 2 + 1], ah[fm], bh[fn][1], bh[fn][3]);
                }
            uint32_t al[2][4];
            ldsm4t(al[0], s0 + 8704 + atrow + acol0);
            ldsm4t(al[1], s0 + 8704 + atrow + acol0 + 32);
            #pragma unroll
            for (int fm = 0; fm < 2; fm++)
                #pragma unroll
                for (int fn = 0; fn < 4; fn++) {
                    mma_bf16(acc[fm][fn * 2],     al[fm], bh[fn][0], bh[fn][2]);
                    mma_bf16(acc[fm][fn * 2 + 1], al[fm], bh[fn][1], bh[fn][3]);
                }
            uint32_t bl[4][4];
            #pragma unroll
            for (int fn = 0; fn < 4; fn++)
                ldsm4(bl[fn], s0 + 27648 + brow + fn * 16 * 80);
            #pragma unroll
            for (int fm = 0; fm < 2; fm++)
                #pragma unroll
                for (int fn = 0; fn < 4; fn++) {
                    mma_bf16(acc[fm][fn * 2],     ah[fm], bl[fn][0], bl[fn][2]);
                    mma_bf16(acc[fm][fn * 2 + 1], ah[fm], bl[fn][1], bl[fn][3]);
                }
        }
        __syncthreads();
    }

    const int fr = lane >> 2;
    const int fc = (lane & 3) * 2;
    #pragma unroll
    for (int fm = 0; fm < 2; fm++) {
        const int row0 = bm + wm * 32 + fm * 16 + fr;
        float s0 = 1.0f / scale[(size_t)b * mpb + row0];
        float s1 = 1.0f / scale[(size_t)b * mpb + row0 + 8];
        float* Cb = C + (size_t)b * c_bs;
        #pragma unroll
        for (int fn = 0; fn < 8; fn++) {
            const int col = bn + wn * 64 + fn * 8 + fc;
            float2 v0, v1;
            v0.x = acc[fm][fn][0] * s0; v0.y = acc[fm][fn][1] * s0;
            v1.x = acc[fm][fn][2] * s1; v1.y = acc[fm][fn][3] * s1;
            *(float2*)(Cb + (size_t)row0 * ldc + col) = v0;
            *(float2*)(Cb + (size_t)(row0 + 8) * ldc + col) = v1;
        }
    }
}

// ---------------------------------------------------------------------------
// Elementwise / transform kernels
// ---------------------------------------------------------------------------
__global__ void split_kernel(const float* __restrict__ in, bf16* __restrict__ hi,
                             bf16* __restrict__ lo, size_t n4) {
    size_t i = (size_t)blockIdx.x * 256 + threadIdx.x;
    if (i >= n4) return;
    float4 v = ((const float4*)in)[i];
    float vv[4] = {v.x, v.y, v.z, v.w};
    bf16 h[4];
    union { __nv_bfloat162 b2[2]; uint2 u; } uh, ul;
    #pragma unroll
    for (int j = 0; j < 4; j++) h[j] = __float2bfloat16(vv[j]);
    uh.b2[0].x = h[0]; uh.b2[0].y = h[1]; uh.b2[1].x = h[2]; uh.b2[1].y = h[3];
    ul.b2[0].x = __float2bfloat16(vv[0] - __bfloat162float(h[0]));
    ul.b2[0].y = __float2bfloat16(vv[1] - __bfloat162float(h[1]));
    ul.b2[1].x = __float2bfloat16(vv[2] - __bfloat162float(h[2]));
    ul.b2[1].y = __float2bfloat16(vv[3] - __bfloat162float(h[3]));
    ((uint2*)hi)[i] = uh.u;
    ((uint2*)lo)[i] = ul.u;
}

__global__ void transpose_split_kernel(const float* __restrict__ in, bf16* __restrict__ ohi,
                                       bf16* __restrict__ olo, int R, int C,
                                       size_t ibs, size_t obs, int scaled) {
    __shared__ float tile[32][33];
    const int bz = blockIdx.z;
    const float* ip = in + (size_t)bz * ibs;
    int c0 = blockIdx.x * 32, r0 = blockIdx.y * 32;
    int tx = threadIdx.x, ty = threadIdx.y;
    #pragma unroll
    for (int i = ty; i < 32; i += 8)
        tile[i][tx] = ip[(size_t)(r0 + i) * C + c0 + tx];
    __syncthreads();
    float er = 1.f;
    if (scaled) er = __expf(g_rowmax[(size_t)bz * LL + r0 + tx] - g_Mb[bz]);
    size_t ob = (size_t)bz * obs;
    #pragma unroll
    for (int i = ty; i < 32; i += 8) {
        float v = tile[tx][i] * er;
        bf16 h = __float2bfloat16(v);
        size_t o = ob + (size_t)(c0 + i) * R + r0 + tx;
        ohi[o] = h;
        olo[o] = __float2bfloat16(v - __bfloat162float(h));
    }
}

__global__ void initstats_kernel() {
    int i = blockIdx.x * 256 + threadIdx.x;
    if (i < NB * LL) { g_rowmax[i] = -INFINITY; g_colsum[i] = 0.f; }
}

__global__ void mbmax_kernel() {
    const int b = blockIdx.x, t = threadIdx.x;
    float4 v = ((const float4*)(g_rowmax + (size_t)b * LL))[t];
    float m = fmaxf(fmaxf(v.x, v.y), fmaxf(v.z, v.w));
    #pragma unroll
    for (int o = 16; o; o >>= 1) m = fmaxf(m, __shfl_xor_sync(~0u, m, o));
    __shared__ float red[8];
    if ((t & 31) == 0) red[t >> 5] = m;
    __syncthreads();
    if (t == 0) {
        float M = red[0];
        #pragma unroll
        for (int i = 1; i < 8; i++) M = fmaxf(M, red[i]);
        g_Mb[b] = M;
    }
}

__global__ __launch_bounds__(256) void dual_exp_kernel() {
    const int b = blockIdx.y;
    const int r0 = blockIdx.x * 64;
    const int w = threadIdx.x >> 5, lane = threadIdx.x & 31;
    const float Mb = g_Mb[b];
    const float* Eb = g_E + (size_t)b * LL * LL;
    bf16* Th = g_Tr_hi + (size_t)b * LL * LL;
    bf16* Tl = g_Tr_lo + (size_t)b * LL * LL;
    float cs[32];
    #pragma unroll
    for (int k = 0; k < 32; k++) cs[k] = 0.f;
    #pragma unroll 1
    for (int j = 0; j < 8; j++) {
        const int row = r0 + w * 8 + j;
        const float rm = g_rowmax[(size_t)b * LL + row];
        const float er = __expf(rm - Mb);
        const float4* src = (const float4*)(Eb + (size_t)row * LL);
        float s = 0.f;
        #pragma unroll
        for (int k = 0; k < 8; k++) {
            float4 v = src[lane + 32 * k];
            float t0 = __expf(v.x - rm), t1 = __expf(v.y - rm);
            float t2 = __expf(v.z - rm), t3 = __expf(v.w - rm);
            s += (t0 + t1) + (t2 + t3);
            cs[k * 4 + 0] += er * t0; cs[k * 4 + 1] += er * t1;
            cs[k * 4 + 2] += er * t2; cs[k * 4 + 3] += er * t3;
            bf16 h0 = __float2bfloat16(t0), h1 = __float2bfloat16(t1);
            bf16 h2 = __float2bfloat16(t2), h3 = __float2bfloat16(t3);
            union { __nv_bfloat162 b2[2]; uint2 u; } uh, ul;
            uh.b2[0].x = h0; uh.b2[0].y = h1; uh.b2[1].x = h2; uh.b2[1].y = h3;
            ul.b2[0].x = __float2bfloat16(t0 - __bfloat162float(h0));
            ul.b2[0].y = __float2bfloat16(t1 - __bfloat162float(h1));
            ul.b2[1].x = __float2bfloat16(t2 - __bfloat162float(h2));
            ul.b2[1].y = __float2bfloat16(t3 - __bfloat162float(h3));
            size_t o = (size_t)row * LL + 4 * (lane + 32 * k);
            *(uint2*)(Th + o) = uh.u;
            *(uint2*)(Tl + o) = ul.u;
        }
        #pragma unroll
        for (int o = 16; o; o >>= 1) s += __shfl_xor_sync(~0u, s, o);
        if (lane == 0) g_rowsum[(size_t)b * LL + row] = s;
    }
    #pragma unroll
    for (int k = 0; k < 8; k++)
        #pragma unroll
        for (int j2 = 0; j2 < 4; j2++)
            atomicAdd(g_colsum + (size_t)b * LL + 4 * (lane + 32 * k) + j2, cs[k * 4 + j2]);
}

// ---------------------------------------------------------------------------
#define SYM(p, s) do { void* _t; cudaGetSymbolAddress(&_t, s); p = decltype(p)(_t); } while (0)

extern "C" void kernel_launch(void* const* d_in, const int* in_sizes, int n_in,
                              void* d_out, int out_size) {
    const float* P   = (const float*)d_in[0];
    const float* Hyp = (const float*)d_in[1];
    const float* W   = (const float*)d_in[2];
    float* out = (float*)d_out;

    bf16 *Xph, *Xpl, *Xhh, *Xhl, *Wth, *Wtl, *Fph, *Fpl, *Fhh, *Fhl;
    bf16 *Hth, *Htl, *Pth, *Ptl, *Trh, *Trl;
    float *E, *rmax, *rsum, *csum;
    SYM(Xph, g_Xp_hi); SYM(Xpl, g_Xp_lo); SYM(Xhh, g_Xh_hi); SYM(Xhl, g_Xh_lo);
    SYM(Wth, g_Wt_hi); SYM(Wtl, g_Wt_lo);
    SYM(Fph, g_Fp_hi); SYM(Fpl, g_Fp_lo); SYM(Fhh, g_Fh_hi); SYM(Fhl, g_Fh_lo);
    SYM(Hth, g_Ht_hi); SYM(Htl, g_Ht_lo); SYM(Pth, g_Pt_hi); SYM(Ptl, g_Pt_lo);
    SYM(Trh, g_Tr_hi); SYM(Trl, g_Tr_lo);
    SYM(E, g_E);
    SYM(rmax, g_rowmax); SYM(rsum, g_rowsum); SYM(csum, g_colsum);

    static int attr_done = 0;
    if (!attr_done) {
        cudaFuncSetAttribute(gemm_split, cudaFuncAttributeMaxDynamicSharedMemorySize, 2 * STG);
        cudaFuncSetAttribute(gemm_splitT, cudaFuncAttributeMaxDynamicSharedMemorySize, 2 * STGT);
        attr_done = 1;
    }

    dim3 t256(256), t32x8(32, 8);
    const int SMG = 2 * STG, SMT = 2 * STGT;

    // input conversions
    split_kernel<<<8192, t256>>>(P, Xph, Xpl, NXD / 4);
    split_kernel<<<8192, t256>>>(Hyp, Xhh, Xhl, NXD / 4);
    transpose_split_kernel<<<dim3(8, 8, 1), t32x8>>>(W, Wth, Wtl, DD, HH, 0, 0, 0);
    transpose_split_kernel<<<dim3(8, 32, NB), t32x8>>>(Hyp, Hth, Htl, LL, DD,
                                                       (size_t)LL * DD, (size_t)LL * DD, 0);

    // proj: F = tanh(X @ W)
    gemm_split<<<dim3(256, 2, 1), t256, SMG>>>(Xph, Xpl, 0, DD, Wth, Wtl, 0, DD, DD, 1,
                                               nullptr, 0, HH, nullptr, 0, Fph, Fpl, nullptr);
    gemm_split<<<dim3(256, 2, 1), t256, SMG>>>(Xhh, Xhl, 0, DD, Wth, Wtl, 0, DD, DD, 1,
                                               nullptr, 0, HH, nullptr, 0, Fhh, Fhl, nullptr);

    // stats init + eij (E + rowmax atomics fused)
    initstats_kernel<<<128, t256>>>();
    gemm_split<<<dim3(8, 8, NB), t256, SMG>>>(Fph, Fpl, (size_t)LL * DD, HH,
                                              Fhh, Fhl, (size_t)LL * DD, HH, HH, 0,
                                              E, (size_t)LL * LL, LL, nullptr, LL,
                                              nullptr, nullptr, rmax);
    mbmax_kernel<<<NB, t256>>>();

    // fused exp/split/rowsum/colsum' pass
    dual_exp_kernel<<<dim3(16, NB), t256>>>();

    // Pt' = transpose(er[p] * P[p,d])
    transpose_split_kernel<<<dim3(8, 32, NB), t32x8>>>(P, Pth, Ptl, LL, DD,
                                                       (size_t)LL * DD, (size_t)LL * DD, 1);

    // betas = (Tr @ Ht) / rowsum
    gemm_split<<<dim3(8, 2, NB), t256, SMG>>>(Trh, Trl, (size_t)LL * LL, LL,
                                              Hth, Htl, (size_t)DD * LL, LL, LL, 2,
                                              out, (size_t)LL * DD, DD, rsum, LL,
                                              nullptr, nullptr, nullptr);
    // alphas = (Tr^T @ Pt') / csum'
    gemm_splitT<<<dim3(8, 2, NB), t256, SMT>>>(Trh, Trl, (size_t)LL * LL, LL,
                                               Pth, Ptl, (size_t)DD * LL, LL, LL,
                                               out + (size_t)NB * LL * DD, (size_t)LL * DD, DD,
                                               csum, LL);
}

// round 15
// speedup vs baseline: 1.2387x; 1.1028x over previous
#include <cuda_runtime.h>
#include <cuda_bf16.h>
#include <math.h>
#include <stdint.h>

#define NB 32
#define LL 1024
#define DD 256
#define HH 256
typedef __nv_bfloat16 bf16;

#define NXD ((size_t)NB * LL * DD)
#define NE  ((size_t)NB * LL * LL)

// ---------------------------------------------------------------------------
// Device scratch
// ---------------------------------------------------------------------------
__device__ __align__(256) bf16 g_Xp_hi[NXD], g_Xp_lo[NXD];
__device__ __align__(256) bf16 g_Xh_hi[NXD], g_Xh_lo[NXD];
__device__ __align__(256) bf16 g_Wt_hi[DD * HH], g_Wt_lo[DD * HH];
__device__ __align__(256) bf16 g_Fp_hi[NXD], g_Fp_lo[NXD];
__device__ __align__(256) bf16 g_Fh_hi[NXD], g_Fh_lo[NXD];
__device__ __align__(256) bf16 g_Ht_hi[NXD], g_Ht_lo[NXD];
__device__ __align__(256) bf16 g_Pt_hi[NXD], g_Pt_lo[NXD];
__device__ __align__(256) bf16 g_Tr_hi[NE], g_Tr_lo[NE];
__device__ __align__(256) float g_rowsum[NB * LL], g_colsum[NB * LL];

// ---------------------------------------------------------------------------
// helpers
// ---------------------------------------------------------------------------
__device__ __forceinline__ uint32_t smem_u32(const void* p) {
    uint32_t a;
    asm("{ .reg .u64 t; cvta.to.shared.u64 t, %1; cvt.u32.u64 %0, t; }" : "=r"(a) : "l"(p));
    return a;
}
__device__ __forceinline__ void cp_async16(uint32_t dst, const void* src) {
    asm volatile("cp.async.cg.shared.global [%0], [%1], 16;" :: "r"(dst), "l"(src));
}
__device__ __forceinline__ void ldsm4(uint32_t* r, uint32_t addr) {
    asm volatile("ldmatrix.sync.aligned.m8n8.x4.shared.b16 {%0,%1,%2,%3}, [%4];"
                 : "=r"(r[0]), "=r"(r[1]), "=r"(r[2]), "=r"(r[3]) : "r"(addr));
}
__device__ __forceinline__ void ldsm4t(uint32_t* r, uint32_t addr) {
    asm volatile("ldmatrix.sync.aligned.m8n8.x4.trans.shared.b16 {%0,%1,%2,%3}, [%4];"
                 : "=r"(r[0]), "=r"(r[1]), "=r"(r[2]), "=r"(r[3]) : "r"(addr));
}
__device__ __forceinline__ void mma_bf16(float* c, const uint32_t* a, uint32_t b0, uint32_t b1) {
    asm volatile(
        "mma.sync.aligned.m16n8k16.row.col.f32.bf16.bf16.f32 "
        "{%0,%1,%2,%3}, {%4,%5,%6,%7}, {%8,%9}, {%0,%1,%2,%3};"
        : "+f"(c[0]), "+f"(c[1]), "+f"(c[2]), "+f"(c[3])
        : "r"(a[0]), "r"(a[1]), "r"(a[2]), "r"(a[3]), "r"(b0), "r"(b1));
}

// stage layout (gemm_split): Ahi 10240 | Alo 10240 | Bhi 10240 | Blo 10240
#define STG  40960
// stage layout (gemm_splitT): Ahi 8704 | Alo 8704 | Bhi 10240 | Blo 10240
#define STGT 37888

// ---------------------------------------------------------------------------
// Fused split-bf16 warp-MMA GEMM: C[m,n] = sum_k A[m,k]*B[n,k]
// All 3 products (hh, lo*hi, hi*lo) in ONE K-sweep per chunk. CTA 128x128,
// BK=32, cp.async double-buffered.
// epi: 1 tanh->split bf16 (Fhi/Flo at b*f_bs);
//      2 fp32 C scaled by 1/scale[b*mpb+m];
//      3 exp->split bf16 (Fhi/Flo at b*f_bs) + atomic row/col sums.
// ---------------------------------------------------------------------------
__global__ __launch_bounds__(256, 2) void gemm_split(
    const bf16* __restrict__ Ahi, const bf16* __restrict__ Alo, size_t a_bs, int lda,
    const bf16* __restrict__ Bhi, const bf16* __restrict__ Blo, size_t b_bs, int ldb,
    int K, int epi,
    float* __restrict__ C, size_t c_bs, int ldc,
    const float* __restrict__ scale, int mpb,
    bf16* __restrict__ Fhi, bf16* __restrict__ Flo, size_t f_bs,
    float* __restrict__ rsumAt, float* __restrict__ csumAt)
{
    extern __shared__ __align__(16) uint8_t sm[];
    const uint32_t smb = smem_u32(sm);
    const int tid = threadIdx.x, lane = tid & 31, wid = tid >> 5;
    const int wm = wid & 3, wn = wid >> 2;
    const int bm = blockIdx.x * 128, bn = blockIdx.y * 128, b = blockIdx.z;
    const int nch = K >> 5;

    const int r0s = tid >> 2,  kv0 = (tid & 3) * 8;
    const int r1s = r0s + 64;

    const bf16* Ah = Ahi + (size_t)b * a_bs;
    const bf16* Al = Alo + (size_t)b * a_bs;
    const bf16* Bh = Bhi + (size_t)b * b_bs;
    const bf16* Bl = Blo + (size_t)b * b_bs;

    auto issue = [&](int ch, int st) {
        const int k0 = ch << 5;
        uint32_t s0 = smb + (uint32_t)st * STG;
        const size_t oa0 = (size_t)(bm + r0s) * lda + k0 + kv0;
        const size_t oa1 = (size_t)(bm + r1s) * lda + k0 + kv0;
        const size_t ob0 = (size_t)(bn + r0s) * ldb + k0 + kv0;
        const size_t ob1 = (size_t)(bn + r1s) * ldb + k0 + kv0;
        cp_async16(s0         + r0s * 80 + kv0 * 2, Ah + oa0);
        cp_async16(s0         + r1s * 80 + kv0 * 2, Ah + oa1);
        cp_async16(s0 + 10240 + r0s * 80 + kv0 * 2, Al + oa0);
        cp_async16(s0 + 10240 + r1s * 80 + kv0 * 2, Al + oa1);
        cp_async16(s0 + 20480 + r0s * 80 + kv0 * 2, Bh + ob0);
        cp_async16(s0 + 20480 + r1s * 80 + kv0 * 2, Bh + ob1);
        cp_async16(s0 + 30720 + r0s * 80 + kv0 * 2, Bl + ob0);
        cp_async16(s0 + 30720 + r1s * 80 + kv0 * 2, Bl + ob1);
        asm volatile("cp.async.commit_group;");
    };

    float acc[2][8][4] = {};
    issue(0, 0);
    for (int ch = 0; ch < nch; ch++) {
        const int st = ch & 1;
        if (ch + 1 < nch) { issue(ch + 1, st ^ 1); asm volatile("cp.async.wait_group 1;"); }
        else              { asm volatile("cp.async.wait_group 0;"); }
        __syncthreads();
        const uint32_t s0 = smb + (uint32_t)st * STG;
        #pragma unroll
        for (int ks = 0; ks < 2; ks++) {
            const uint32_t colb = (uint32_t)(ks * 16 + (lane >> 4) * 8) * 2;
            const uint32_t arow = (uint32_t)(wm * 32 + (lane & 15)) * 80 + colb;
            const uint32_t brow = (uint32_t)(wn * 64 + (lane & 15)) * 80 + colb;
            uint32_t ah[2][4];
            ldsm4(ah[0], s0 + arow);
            ldsm4(ah[1], s0 + arow + 16 * 80);
            uint32_t bh[4][4];
            #pragma unroll
            for (int fn = 0; fn < 4; fn++)
                ldsm4(bh[fn], s0 + 20480 + brow + fn * 16 * 80);
            #pragma unroll
            for (int fm = 0; fm < 2; fm++)
                #pragma unroll
                for (int fn = 0; fn < 4; fn++) {
                    mma_bf16(acc[fm][fn * 2],     ah[fm], bh[fn][0], bh[fn][2]);
                    mma_bf16(acc[fm][fn * 2 + 1], ah[fm], bh[fn][1], bh[fn][3]);
                }
            uint32_t al[2][4];
            ldsm4(al[0], s0 + 10240 + arow);
            ldsm4(al[1], s0 + 10240 + arow + 16 * 80);
            #pragma unroll
            for (int fm = 0; fm < 2; fm++)
                #pragma unroll
                for (int fn = 0; fn < 4; fn++) {
                    mma_bf16(acc[fm][fn * 2],     al[fm], bh[fn][0], bh[fn][2]);
                    mma_bf16(acc[fm][fn * 2 + 1], al[fm], bh[fn][1], bh[fn][3]);
                }
            uint32_t bl[4][4];
            #pragma unroll
            for (int fn = 0; fn < 4; fn++)
                ldsm4(bl[fn], s0 + 30720 + brow + fn * 16 * 80);
            #pragma unroll
            for (int fm = 0; fm < 2; fm++)
                #pragma unroll
                for (int fn = 0; fn < 4; fn++) {
                    mma_bf16(acc[fm][fn * 2],     ah[fm], bl[fn][0], bl[fn][2]);
                    mma_bf16(acc[fm][fn * 2 + 1], ah[fm], bl[fn][1], bl[fn][3]);
                }
        }
        __syncthreads();
    }

    const int fr = lane >> 2;
    const int fc = (lane & 3) * 2;

    if (epi == 3) {
        #pragma unroll
        for (int fm = 0; fm < 2; fm++)
            #pragma unroll
            for (int fn = 0; fn < 8; fn++)
                #pragma unroll
                for (int j = 0; j < 4; j++)
                    acc[fm][fn][j] = __expf(acc[fm][fn][j]);
        bf16* Fh_ = Fhi + (size_t)b * f_bs;
        bf16* Fl_ = Flo + (size_t)b * f_bs;
        #pragma unroll
        for (int fm = 0; fm < 2; fm++) {
            const int row0 = bm + wm * 32 + fm * 16 + fr;
            #pragma unroll
            for (int half = 0; half < 2; half++) {
                const size_t gr = (size_t)(row0 + half * 8);
                #pragma unroll
                for (int fn = 0; fn < 8; fn++) {
                    const int col = bn + wn * 64 + fn * 8 + fc;
                    float v0 = acc[fm][fn][half * 2];
                    float v1 = acc[fm][fn][half * 2 + 1];
                    bf16 h0 = __float2bfloat16(v0), h1 = __float2bfloat16(v1);
                    __nv_bfloat162 hp, lp;
                    hp.x = h0; hp.y = h1;
                    lp.x = __float2bfloat16(v0 - __bfloat162float(h0));
                    lp.y = __float2bfloat16(v1 - __bfloat162float(h1));
                    size_t o = gr * ldc + col;
                    *(__nv_bfloat162*)(Fh_ + o) = hp;
                    *(__nv_bfloat162*)(Fl_ + o) = lp;
                }
            }
        }
        // row sums: reduce over fc-lanes (bits 0,1)
        #pragma unroll
        for (int fm = 0; fm < 2; fm++)
            #pragma unroll
            for (int half = 0; half < 2; half++) {
                float rs = 0.f;
                #pragma unroll
                for (int fn = 0; fn < 8; fn++)
                    rs += acc[fm][fn][half * 2] + acc[fm][fn][half * 2 + 1];
                rs += __shfl_xor_sync(~0u, rs, 1);
                rs += __shfl_xor_sync(~0u, rs, 2);
                if ((lane & 3) == 0)
                    atomicAdd(rsumAt + (size_t)b * LL + bm + wm * 32 + fm * 16 + fr + half * 8, rs);
            }
        // col sums: reduce over fr-lanes (bits 2,3,4)
        #pragma unroll
        for (int fn = 0; fn < 8; fn++) {
            float c0 = 0.f, c1 = 0.f;
            #pragma unroll
            for (int fm = 0; fm < 2; fm++)
                #pragma unroll
                for (int half = 0; half < 2; half++) {
                    c0 += acc[fm][fn][half * 2];
                    c1 += acc[fm][fn][half * 2 + 1];
                }
            #pragma unroll
            for (int o = 4; o <= 16; o <<= 1) {
                c0 += __shfl_xor_sync(~0u, c0, o);
                c1 += __shfl_xor_sync(~0u, c1, o);
            }
            if (lane < 4) {
                float* cp = csumAt + (size_t)b * LL + bn + wn * 64 + fn * 8 + fc;
                atomicAdd(cp, c0);
                atomicAdd(cp + 1, c1);
            }
        }
        return;
    }

    #pragma unroll
    for (int fm = 0; fm < 2; fm++) {
        const int row0 = bm + wm * 32 + fm * 16 + fr;
        if (epi == 1) {
            bf16* Fh_ = Fhi + (size_t)b * f_bs;
            bf16* Fl_ = Flo + (size_t)b * f_bs;
            #pragma unroll
            for (int half = 0; half < 2; half++) {
                const size_t gr = (size_t)(row0 + half * 8);
                #pragma unroll
                for (int fn = 0; fn < 8; fn++) {
                    const int col = bn + wn * 64 + fn * 8 + fc;
                    float v0 = tanhf(acc[fm][fn][half * 2]);
                    float v1 = tanhf(acc[fm][fn][half * 2 + 1]);
                    bf16 h0 = __float2bfloat16(v0), h1 = __float2bfloat16(v1);
                    __nv_bfloat162 hp, lp;
                    hp.x = h0; hp.y = h1;
                    lp.x = __float2bfloat16(v0 - __bfloat162float(h0));
                    lp.y = __float2bfloat16(v1 - __bfloat162float(h1));
                    size_t o = gr * ldc + col;
                    *(__nv_bfloat162*)(Fh_ + o) = hp;
                    *(__nv_bfloat162*)(Fl_ + o) = lp;
                }
            }
        } else {
            float s0 = 1.0f / scale[(size_t)b * mpb + row0];
            float s1 = 1.0f / scale[(size_t)b * mpb + row0 + 8];
            float* Cb = C + (size_t)b * c_bs;
            #pragma unroll
            for (int fn = 0; fn < 8; fn++) {
                const int col = bn + wn * 64 + fn * 8 + fc;
                float2 v0, v1;
                v0.x = acc[fm][fn][0] * s0; v0.y = acc[fm][fn][1] * s0;
                v1.x = acc[fm][fn][2] * s1; v1.y = acc[fm][fn][3] * s1;
                *(float2*)(Cb + (size_t)row0 * ldc + col) = v0;
                *(float2*)(Cb + (size_t)(row0 + 8) * ldc + col) = v1;
            }
        }
    }
}

// ---------------------------------------------------------------------------
// Fused trans-A variant (alphas): C[m,n] = sum_k A[k,m]*B[n,k]
// ---------------------------------------------------------------------------
__global__ __launch_bounds__(256, 2) void gemm_splitT(
    const bf16* __restrict__ Ahi, const bf16* __restrict__ Alo, size_t a_bs, int lda,
    const bf16* __restrict__ Bhi, const bf16* __restrict__ Blo, size_t b_bs, int ldb,
    int K,
    float* __restrict__ C, size_t c_bs, int ldc,
    const float* __restrict__ scale, int mpb)
{
    extern __shared__ __align__(16) uint8_t sm[];
    const uint32_t smb = smem_u32(sm);
    const int tid = threadIdx.x, lane = tid & 31, wid = tid >> 5;
    const int wm = wid & 3, wn = wid >> 2;
    const int bm = blockIdx.x * 128, bn = blockIdx.y * 128, b = blockIdx.z;
    const int nch = K >> 5;

    const int ar  = tid >> 4,  akv = (tid & 15) * 8;
    const int r0s = tid >> 2,  kv0 = (tid & 3) * 8;
    const int r1s = r0s + 64;

    const bf16* Ah = Ahi + (size_t)b * a_bs;
    const bf16* Al = Alo + (size_t)b * a_bs;
    const bf16* Bh = Bhi + (size_t)b * b_bs;
    const bf16* Bl = Blo + (size_t)b * b_bs;

    auto issue = [&](int ch, int st) {
        const int k0 = ch << 5;
        uint32_t s0 = smb + (uint32_t)st * STGT;
        const size_t oa0 = (size_t)(k0 + ar) * lda + bm + akv;
        const size_t oa1 = (size_t)(k0 + ar + 16) * lda + bm + akv;
        const size_t ob0 = (size_t)(bn + r0s) * ldb + k0 + kv0;
        const size_t ob1 = (size_t)(bn + r1s) * ldb + k0 + kv0;
        cp_async16(s0         + ar * 272 + akv * 2,        Ah + oa0);
        cp_async16(s0         + (ar + 16) * 272 + akv * 2, Ah + oa1);
        cp_async16(s0 + 8704  + ar * 272 + akv * 2,        Al + oa0);
        cp_async16(s0 + 8704  + (ar + 16) * 272 + akv * 2, Al + oa1);
        cp_async16(s0 + 17408 + r0s * 80 + kv0 * 2, Bh + ob0);
        cp_async16(s0 + 17408 + r1s * 80 + kv0 * 2, Bh + ob1);
        cp_async16(s0 + 27648 + r0s * 80 + kv0 * 2, Bl + ob0);
        cp_async16(s0 + 27648 + r1s * 80 + kv0 * 2, Bl + ob1);
        asm volatile("cp.async.commit_group;");
    };

    float acc[2][8][4] = {};
    issue(0, 0);
    for (int ch = 0; ch < nch; ch++) {
        const int st = ch & 1;
        if (ch + 1 < nch) { issue(ch + 1, st ^ 1); asm volatile("cp.async.wait_group 1;"); }
        else              { asm volatile("cp.async.wait_group 0;"); }
        __syncthreads();
        const uint32_t s0 = smb + (uint32_t)st * STGT;
        #pragma unroll
        for (int ks = 0; ks < 2; ks++) {
            const uint32_t atrow = (uint32_t)(ks * 16 + ((lane >> 4) << 3) + (lane & 7)) * 272;
            const uint32_t acol0 = (uint32_t)(wm * 32 + ((lane >> 3) & 1) * 8) * 2;
            const uint32_t colb  = (uint32_t)(ks * 16 + (lane >> 4) * 8) * 2;
            const uint32_t brow  = (uint32_t)(wn * 64 + (lane & 15)) * 80 + colb;
            uint32_t ah[2][4];
            ldsm4t(ah[0], s0 + atrow + acol0);
            ldsm4t(ah[1], s0 + atrow + acol0 + 32);
            uint32_t bh[4][4];
            #pragma unroll
            for (int fn = 0; fn < 4; fn++)
                ldsm4(bh[fn], s0 + 17408 + brow + fn * 16 * 80);
            #pragma unroll
            for (int fm = 0; fm < 2; fm++)
                #pragma unroll
                for (int fn = 0; fn < 4; fn++) {
                    mma_bf16(acc[fm][fn * 2],     ah[fm], bh[fn][0], bh[fn][2]);
                    mma_bf16(acc[fm][fn * 2 + 1], ah[fm], bh[fn][1], bh[fn][3]);
                }
            uint32_t al[2][4];
            ldsm4t(al[0], s0 + 8704 + atrow + acol0);
            ldsm4t(al[1], s0 + 8704 + atrow + acol0 + 32);
            #pragma unroll
            for (int fm = 0; fm < 2; fm++)
                #pragma unroll
                for (int fn = 0; fn < 4; fn++) {
                    mma_bf16(acc[fm][fn * 2],     al[fm], bh[fn][0], bh[fn][2]);
                    mma_bf16(acc[fm][fn * 2 + 1], al[fm], bh[fn][1], bh[fn][3]);
                }
            uint32_t bl[4][4];
            #pragma unroll
            for (int fn = 0; fn < 4; fn++)
                ldsm4(bl[fn], s0 + 27648 + brow + fn * 16 * 80);
            #pragma unroll
            for (int fm = 0; fm < 2; fm++)
                #pragma unroll
                for (int fn = 0; fn < 4; fn++) {
                    mma_bf16(acc[fm][fn * 2],     ah[fm], bl[fn][0], bl[fn][2]);
                    mma_bf16(acc[fm][fn * 2 + 1], ah[fm], bl[fn][1], bl[fn][3]);
                }
        }
        __syncthreads();
    }

    const int fr = lane >> 2;
    const int fc = (lane & 3) * 2;
    #pragma unroll
    for (int fm = 0; fm < 2; fm++) {
        const int row0 = bm + wm * 32 + fm * 16 + fr;
        float s0 = 1.0f / scale[(size_t)b * mpb + row0];
        float s1 = 1.0f / scale[(size_t)b * mpb + row0 + 8];
        float* Cb = C + (size_t)b * c_bs;
        #pragma unroll
        for (int fn = 0; fn < 8; fn++) {
            const int col = bn + wn * 64 + fn * 8 + fc;
            float2 v0, v1;
            v0.x = acc[fm][fn][0] * s0; v0.y = acc[fm][fn][1] * s0;
            v1.x = acc[fm][fn][2] * s1; v1.y = acc[fm][fn][3] * s1;
            *(float2*)(Cb + (size_t)row0 * ldc + col) = v0;
            *(float2*)(Cb + (size_t)(row0 + 8) * ldc + col) = v1;
        }
    }
}

// ---------------------------------------------------------------------------
// Elementwise / transform kernels
// ---------------------------------------------------------------------------
__global__ void split_kernel(const float* __restrict__ in, bf16* __restrict__ hi,
                             bf16* __restrict__ lo, size_t n4) {
    size_t i = (size_t)blockIdx.x * 256 + threadIdx.x;
    if (i >= n4) return;
    float4 v = ((const float4*)in)[i];
    float vv[4] = {v.x, v.y, v.z, v.w};
    bf16 h[4];
    union { __nv_bfloat162 b2[2]; uint2 u; } uh, ul;
    #pragma unroll
    for (int j = 0; j < 4; j++) h[j] = __float2bfloat16(vv[j]);
    uh.b2[0].x = h[0]; uh.b2[0].y = h[1]; uh.b2[1].x = h[2]; uh.b2[1].y = h[3];
    ul.b2[0].x = __float2bfloat16(vv[0] - __bfloat162float(h[0]));
    ul.b2[0].y = __float2bfloat16(vv[1] - __bfloat162float(h[1]));
    ul.b2[1].x = __float2bfloat16(vv[2] - __bfloat162float(h[2]));
    ul.b2[1].y = __float2bfloat16(vv[3] - __bfloat162float(h[3]));
    ((uint2*)hi)[i] = uh.u;
    ((uint2*)lo)[i] = ul.u;
}

__global__ void transpose_split_kernel(const float* __restrict__ in, bf16* __restrict__ ohi,
                                       bf16* __restrict__ olo, int R, int C,
                                       size_t ibs, size_t obs) {
    __shared__ float tile[32][33];
    const int bz = blockIdx.z;
    const float* ip = in + (size_t)bz * ibs;
    int c0 = blockIdx.x * 32, r0 = blockIdx.y * 32;
    int tx = threadIdx.x, ty = threadIdx.y;
    #pragma unroll
    for (int i = ty; i < 32; i += 8)
        tile[i][tx] = ip[(size_t)(r0 + i) * C + c0 + tx];
    __syncthreads();
    size_t ob = (size_t)bz * obs;
    #pragma unroll
    for (int i = ty; i < 32; i += 8) {
        float v = tile[tx][i];
        bf16 h = __float2bfloat16(v);
        size_t o = ob + (size_t)(c0 + i) * R + r0 + tx;
        ohi[o] = h;
        olo[o] = __float2bfloat16(v - __bfloat162float(h));
    }
}

__global__ void initstats_kernel() {
    int i = blockIdx.x * 256 + threadIdx.x;
    if (i < NB * LL) { g_rowsum[i] = 0.f; g_colsum[i] = 0.f; }
}

// ---------------------------------------------------------------------------
#define SYM(p, s) do { void* _t; cudaGetSymbolAddress(&_t, s); p = decltype(p)(_t); } while (0)

extern "C" void kernel_launch(void* const* d_in, const int* in_sizes, int n_in,
                              void* d_out, int out_size) {
    const float* P   = (const float*)d_in[0];
    const float* Hyp = (const float*)d_in[1];
    const float* W   = (const float*)d_in[2];
    float* out = (float*)d_out;

    bf16 *Xph, *Xpl, *Xhh, *Xhl, *Wth, *Wtl, *Fph, *Fpl, *Fhh, *Fhl;
    bf16 *Hth, *Htl, *Pth, *Ptl, *Trh, *Trl;
    float *rsum, *csum;
    SYM(Xph, g_Xp_hi); SYM(Xpl, g_Xp_lo); SYM(Xhh, g_Xh_hi); SYM(Xhl, g_Xh_lo);
    SYM(Wth, g_Wt_hi); SYM(Wtl, g_Wt_lo);
    SYM(Fph, g_Fp_hi); SYM(Fpl, g_Fp_lo); SYM(Fhh, g_Fh_hi); SYM(Fhl, g_Fh_lo);
    SYM(Hth, g_Ht_hi); SYM(Htl, g_Ht_lo); SYM(Pth, g_Pt_hi); SYM(Ptl, g_Pt_lo);
    SYM(Trh, g_Tr_hi); SYM(Trl, g_Tr_lo);
    SYM(rsum, g_rowsum); SYM(csum, g_colsum);

    static int attr_done = 0;
    if (!attr_done) {
        cudaFuncSetAttribute(gemm_split, cudaFuncAttributeMaxDynamicSharedMemorySize, 2 * STG);
        cudaFuncSetAttribute(gemm_splitT, cudaFuncAttributeMaxDynamicSharedMemorySize, 2 * STGT);
        attr_done = 1;
    }

    dim3 t256(256), t32x8(32, 8);
    const int SMG = 2 * STG, SMT = 2 * STGT;

    // input conversions
    split_kernel<<<8192, t256>>>(P, Xph, Xpl, NXD / 4);
    split_kernel<<<8192, t256>>>(Hyp, Xhh, Xhl, NXD / 4);
    transpose_split_kernel<<<dim3(8, 8, 1), t32x8>>>(W, Wth, Wtl, DD, HH, 0, 0);
    transpose_split_kernel<<<dim3(8, 32, NB), t32x8>>>(Hyp, Hth, Htl, LL, DD,
                                                       (size_t)LL * DD, (size_t)LL * DD);
    transpose_split_kernel<<<dim3(8, 32, NB), t32x8>>>(P, Pth, Ptl, LL, DD,
                                                       (size_t)LL * DD, (size_t)LL * DD);
    initstats_kernel<<<128, t256>>>();

    // proj: F = tanh(X @ W)  (batch folded into M, f_bs=0)
    gemm_split<<<dim3(256, 2, 1), t256, SMG>>>(Xph, Xpl, 0, DD, Wth, Wtl, 0, DD, DD, 1,
                                               nullptr, 0, HH, nullptr, 0, Fph, Fpl, 0,
                                               nullptr, nullptr);
    gemm_split<<<dim3(256, 2, 1), t256, SMG>>>(Xhh, Xhl, 0, DD, Wth, Wtl, 0, DD, DD, 1,
                                               nullptr, 0, HH, nullptr, 0, Fhh, Fhl, 0,
                                               nullptr, nullptr);

    // eij -> Tr = exp(Fp@Fh^T) (split bf16, batch stride LL*LL) + row/col sums
    gemm_split<<<dim3(8, 8, NB), t256, SMG>>>(Fph, Fpl, (size_t)LL * DD, HH,
                                              Fhh, Fhl, (size_t)LL * DD, HH, HH, 3,
                                              nullptr, 0, LL, nullptr, LL,
                                              Trh, Trl, (size_t)LL * LL, rsum, csum);

    // betas = (Tr @ Ht) / rowsum
    gemm_split<<<dim3(8, 2, NB), t256, SMG>>>(Trh, Trl, (size_t)LL * LL, LL,
                                              Hth, Htl, (size_t)DD * LL, LL, LL, 2,
                                              out, (size_t)LL * DD, DD, rsum, LL,
                                              nullptr, nullptr, 0, nullptr, nullptr);
    // alphas = (Tr^T @ Pt) / colsum
    gemm_splitT<<<dim3(8, 2, NB), t256, SMT>>>(Trh, Trl, (size_t)LL * LL, LL,
                                               Pth, Ptl, (size_t)DD * LL, LL, LL,
                                               out + (size_t)NB * LL * DD, (size_t)LL * DD, DD,
                                               csum, LL);
}

// round 16
// speedup vs baseline: 1.3925x; 1.1242x over previous
#include <cuda_runtime.h>
#include <cuda_bf16.h>
#include <math.h>
#include <stdint.h>

#define NB 32
#define LL 1024
#define DD 256
#define HH 256
typedef __nv_bfloat16 bf16;

#define NXD ((size_t)NB * LL * DD)
#define NE  ((size_t)NB * LL * LL)

// ---------------------------------------------------------------------------
// Device scratch
// ---------------------------------------------------------------------------
__device__ __align__(256) bf16 g_Xp_hi[NXD], g_Xp_lo[NXD];
__device__ __align__(256) bf16 g_Xh_hi[NXD], g_Xh_lo[NXD];
__device__ __align__(256) bf16 g_Wt_hi[DD * HH], g_Wt_lo[DD * HH];
__device__ __align__(256) bf16 g_Fp_hi[NXD], g_Fp_lo[NXD];
__device__ __align__(256) bf16 g_Fh_hi[NXD], g_Fh_lo[NXD];
__device__ __align__(256) bf16 g_Ht_hi[NXD], g_Ht_lo[NXD];
__device__ __align__(256) bf16 g_Pt_hi[NXD], g_Pt_lo[NXD];
__device__ __align__(256) bf16 g_Tr_hi[NE], g_Tr_lo[NE];
__device__ __align__(256) float g_rowsum[NB * LL], g_colsum[NB * LL];

// ---------------------------------------------------------------------------
// helpers
// ---------------------------------------------------------------------------
__device__ __forceinline__ uint32_t smem_u32(const void* p) {
    uint32_t a;
    asm("{ .reg .u64 t; cvta.to.shared.u64 t, %1; cvt.u32.u64 %0, t; }" : "=r"(a) : "l"(p));
    return a;
}
__device__ __forceinline__ void cp_async16(uint32_t dst, const void* src) {
    asm volatile("cp.async.cg.shared.global [%0], [%1], 16;" :: "r"(dst), "l"(src));
}
__device__ __forceinline__ void ldsm4(uint32_t* r, uint32_t addr) {
    asm volatile("ldmatrix.sync.aligned.m8n8.x4.shared.b16 {%0,%1,%2,%3}, [%4];"
                 : "=r"(r[0]), "=r"(r[1]), "=r"(r[2]), "=r"(r[3]) : "r"(addr));
}
__device__ __forceinline__ void ldsm4t(uint32_t* r, uint32_t addr) {
    asm volatile("ldmatrix.sync.aligned.m8n8.x4.trans.shared.b16 {%0,%1,%2,%3}, [%4];"
                 : "=r"(r[0]), "=r"(r[1]), "=r"(r[2]), "=r"(r[3]) : "r"(addr));
}
__device__ __forceinline__ void mma_bf16(float* c, const uint32_t* a, uint32_t b0, uint32_t b1) {
    asm volatile(
        "mma.sync.aligned.m16n8k16.row.col.f32.bf16.bf16.f32 "
        "{%0,%1,%2,%3}, {%4,%5,%6,%7}, {%8,%9}, {%0,%1,%2,%3};"
        : "+f"(c[0]), "+f"(c[1]), "+f"(c[2]), "+f"(c[3])
        : "r"(a[0]), "r"(a[1]), "r"(a[2]), "r"(a[3]), "r"(b0), "r"(b1));
}

// stage layouts
#define STG  40960   // normal: Ahi 10240 | Alo 10240 | Bhi 10240 | Blo 10240
// trans-A layout (within STG stride): Ahi 8704 | Alo 8704 | Bhi 10240 | Blo 10240

// ---------------------------------------------------------------------------
// Fused split-bf16 warp-MMA GEMM (normal A). epi: 1 tanh->split bf16;
// 3 exp->split bf16 + atomic row/col sums. Optional second input set
// (A2/F2, selected when blockIdx.z==1) merges the two proj GEMMs.
// ---------------------------------------------------------------------------
__global__ __launch_bounds__(256, 2) void gemm_split(
    const bf16* __restrict__ Ahi, const bf16* __restrict__ Alo, size_t a_bs, int lda,
    const bf16* __restrict__ Bhi, const bf16* __restrict__ Blo, size_t b_bs, int ldb,
    int K, int epi,
    bf16* __restrict__ Fhi, bf16* __restrict__ Flo, size_t f_bs, int ldc,
    float* __restrict__ rsumAt, float* __restrict__ csumAt,
    const bf16* __restrict__ A2hi, const bf16* __restrict__ A2lo,
    bf16* __restrict__ F2hi, bf16* __restrict__ F2lo)
{
    extern __shared__ __align__(16) uint8_t sm[];
    const uint32_t smb = smem_u32(sm);
    const int tid = threadIdx.x, lane = tid & 31, wid = tid >> 5;
    const int wm = wid & 3, wn = wid >> 2;
    const int bm = blockIdx.x * 128, bn = blockIdx.y * 128, b = blockIdx.z;
    const int nch = K >> 5;

    const int r0s = tid >> 2,  kv0 = (tid & 3) * 8;
    const int r1s = r0s + 64;

    const int alt = (A2hi != nullptr) && (b == 1);
    const bf16* Ah = (alt ? A2hi : Ahi) + (size_t)b * a_bs;
    const bf16* Al = (alt ? A2lo : Alo) + (size_t)b * a_bs;
    const bf16* Bh = Bhi + (size_t)b * b_bs;
    const bf16* Bl = Blo + (size_t)b * b_bs;

    auto issue = [&](int ch, int st) {
        const int k0 = ch << 5;
        uint32_t s0 = smb + (uint32_t)st * STG;
        const size_t oa0 = (size_t)(bm + r0s) * lda + k0 + kv0;
        const size_t oa1 = (size_t)(bm + r1s) * lda + k0 + kv0;
        const size_t ob0 = (size_t)(bn + r0s) * ldb + k0 + kv0;
        const size_t ob1 = (size_t)(bn + r1s) * ldb + k0 + kv0;
        cp_async16(s0         + r0s * 80 + kv0 * 2, Ah + oa0);
        cp_async16(s0         + r1s * 80 + kv0 * 2, Ah + oa1);
        cp_async16(s0 + 10240 + r0s * 80 + kv0 * 2, Al + oa0);
        cp_async16(s0 + 10240 + r1s * 80 + kv0 * 2, Al + oa1);
        cp_async16(s0 + 20480 + r0s * 80 + kv0 * 2, Bh + ob0);
        cp_async16(s0 + 20480 + r1s * 80 + kv0 * 2, Bh + ob1);
        cp_async16(s0 + 30720 + r0s * 80 + kv0 * 2, Bl + ob0);
        cp_async16(s0 + 30720 + r1s * 80 + kv0 * 2, Bl + ob1);
        asm volatile("cp.async.commit_group;");
    };

    float acc[2][8][4] = {};
    issue(0, 0);
    for (int ch = 0; ch < nch; ch++) {
        const int st = ch & 1;
        if (ch + 1 < nch) { issue(ch + 1, st ^ 1); asm volatile("cp.async.wait_group 1;"); }
        else              { asm volatile("cp.async.wait_group 0;"); }
        __syncthreads();
        const uint32_t s0 = smb + (uint32_t)st * STG;
        #pragma unroll
        for (int ks = 0; ks < 2; ks++) {
            const uint32_t colb = (uint32_t)(ks * 16 + (lane >> 4) * 8) * 2;
            const uint32_t arow = (uint32_t)(wm * 32 + (lane & 15)) * 80 + colb;
            const uint32_t brow = (uint32_t)(wn * 64 + (lane & 15)) * 80 + colb;
            uint32_t ah[2][4];
            ldsm4(ah[0], s0 + arow);
            ldsm4(ah[1], s0 + arow + 16 * 80);
            uint32_t bh[4][4];
            #pragma unroll
            for (int fn = 0; fn < 4; fn++)
                ldsm4(bh[fn], s0 + 20480 + brow + fn * 16 * 80);
            #pragma unroll
            for (int fm = 0; fm < 2; fm++)
                #pragma unroll
                for (int fn = 0; fn < 4; fn++) {
                    mma_bf16(acc[fm][fn * 2],     ah[fm], bh[fn][0], bh[fn][2]);
                    mma_bf16(acc[fm][fn * 2 + 1], ah[fm], bh[fn][1], bh[fn][3]);
                }
            uint32_t al[2][4];
            ldsm4(al[0], s0 + 10240 + arow);
            ldsm4(al[1], s0 + 10240 + arow + 16 * 80);
            #pragma unroll
            for (int fm = 0; fm < 2; fm++)
                #pragma unroll
                for (int fn = 0; fn < 4; fn++) {
                    mma_bf16(acc[fm][fn * 2],     al[fm], bh[fn][0], bh[fn][2]);
                    mma_bf16(acc[fm][fn * 2 + 1], al[fm], bh[fn][1], bh[fn][3]);
                }
            uint32_t bl[4][4];
            #pragma unroll
            for (int fn = 0; fn < 4; fn++)
                ldsm4(bl[fn], s0 + 30720 + brow + fn * 16 * 80);
            #pragma unroll
            for (int fm = 0; fm < 2; fm++)
                #pragma unroll
                for (int fn = 0; fn < 4; fn++) {
                    mma_bf16(acc[fm][fn * 2],     ah[fm], bl[fn][0], bl[fn][2]);
                    mma_bf16(acc[fm][fn * 2 + 1], ah[fm], bl[fn][1], bl[fn][3]);
                }
        }
        __syncthreads();
    }

    const int fr = lane >> 2;
    const int fc = (lane & 3) * 2;
    bf16* Fh_ = (alt ? F2hi : Fhi) + (size_t)b * f_bs;
    bf16* Fl_ = (alt ? F2lo : Flo) + (size_t)b * f_bs;

    if (epi == 3) {
        #pragma unroll
        for (int fm = 0; fm < 2; fm++)
            #pragma unroll
            for (int fn = 0; fn < 8; fn++)
                #pragma unroll
                for (int j = 0; j < 4; j++)
                    acc[fm][fn][j] = __expf(acc[fm][fn][j]);
        #pragma unroll
        for (int fm = 0; fm < 2; fm++) {
            const int row0 = bm + wm * 32 + fm * 16 + fr;
            #pragma unroll
            for (int half = 0; half < 2; half++) {
                const size_t gr = (size_t)(row0 + half * 8);
                #pragma unroll
                for (int fn = 0; fn < 8; fn++) {
                    const int col = bn + wn * 64 + fn * 8 + fc;
                    float v0 = acc[fm][fn][half * 2];
                    float v1 = acc[fm][fn][half * 2 + 1];
                    bf16 h0 = __float2bfloat16(v0), h1 = __float2bfloat16(v1);
                    __nv_bfloat162 hp, lp;
                    hp.x = h0; hp.y = h1;
                    lp.x = __float2bfloat16(v0 - __bfloat162float(h0));
                    lp.y = __float2bfloat16(v1 - __bfloat162float(h1));
                    size_t o = gr * ldc + col;
                    *(__nv_bfloat162*)(Fh_ + o) = hp;
                    *(__nv_bfloat162*)(Fl_ + o) = lp;
                }
            }
        }
        #pragma unroll
        for (int fm = 0; fm < 2; fm++)
            #pragma unroll
            for (int half = 0; half < 2; half++) {
                float rs = 0.f;
                #pragma unroll
                for (int fn = 0; fn < 8; fn++)
                    rs += acc[fm][fn][half * 2] + acc[fm][fn][half * 2 + 1];
                rs += __shfl_xor_sync(~0u, rs, 1);
                rs += __shfl_xor_sync(~0u, rs, 2);
                if ((lane & 3) == 0)
                    atomicAdd(rsumAt + (size_t)b * LL + bm + wm * 32 + fm * 16 + fr + half * 8, rs);
            }
        #pragma unroll
        for (int fn = 0; fn < 8; fn++) {
            float c0 = 0.f, c1 = 0.f;
            #pragma unroll
            for (int fm = 0; fm < 2; fm++)
                #pragma unroll
                for (int half = 0; half < 2; half++) {
                    c0 += acc[fm][fn][half * 2];
                    c1 += acc[fm][fn][half * 2 + 1];
                }
            #pragma unroll
            for (int o = 4; o <= 16; o <<= 1) {
                c0 += __shfl_xor_sync(~0u, c0, o);
                c1 += __shfl_xor_sync(~0u, c1, o);
            }
            if (lane < 4) {
                float* cp = csumAt + (size_t)b * LL + bn + wn * 64 + fn * 8 + fc;
                atomicAdd(cp, c0);
                atomicAdd(cp + 1, c1);
            }
        }
        return;
    }

    // epi == 1: tanh -> split bf16
    #pragma unroll
    for (int fm = 0; fm < 2; fm++) {
        const int row0 = bm + wm * 32 + fm * 16 + fr;
        #pragma unroll
        for (int half = 0; half < 2; half++) {
            const size_t gr = (size_t)(row0 + half * 8);
            #pragma unroll
            for (int fn = 0; fn < 8; fn++) {
                const int col = bn + wn * 64 + fn * 8 + fc;
                float v0 = tanhf(acc[fm][fn][half * 2]);
                float v1 = tanhf(acc[fm][fn][half * 2 + 1]);
                bf16 h0 = __float2bfloat16(v0), h1 = __float2bfloat16(v1);
                __nv_bfloat162 hp, lp;
                hp.x = h0; hp.y = h1;
                lp.x = __float2bfloat16(v0 - __bfloat162float(h0));
                lp.y = __float2bfloat16(v1 - __bfloat162float(h1));
                size_t o = gr * ldc + col;
                *(__nv_bfloat162*)(Fh_ + o) = hp;
                *(__nv_bfloat162*)(Fl_ + o) = lp;
            }
        }
    }
}

// ---------------------------------------------------------------------------
// Merged tail kernel: z<NB -> betas (normal A = Tr), z>=NB -> alphas
// (trans A = Tr read as [k,m] via ldmatrix.trans). Both: fp32 C scaled by
// 1/scale[b*LL+m].
// ---------------------------------------------------------------------------
__global__ __launch_bounds__(256, 2) void gemm_tail(
    const bf16* __restrict__ Trh, const bf16* __restrict__ Trl,
    const bf16* __restrict__ Hth, const bf16* __restrict__ Htl,
    const bf16* __restrict__ Pth, const bf16* __restrict__ Ptl,
    float* __restrict__ out,
    const float* __restrict__ rsum, const float* __restrict__ csum)
{
    extern __shared__ __align__(16) uint8_t sm[];
    const uint32_t smb = smem_u32(sm);
    const int tid = threadIdx.x, lane = tid & 31, wid = tid >> 5;
    const int wm = wid & 3, wn = wid >> 2;
    const int bm = blockIdx.x * 128, bn = blockIdx.y * 128;
    const int z = blockIdx.z;
    const int isT = z >= NB;
    const int b = z & (NB - 1);
    const int nch = LL >> 5;

    const bf16* Ah = Trh + (size_t)b * LL * LL;
    const bf16* Al = Trl + (size_t)b * LL * LL;
    const bf16* Bh = (isT ? Pth : Hth) + (size_t)b * DD * LL;
    const bf16* Bl = (isT ? Ptl : Htl) + (size_t)b * DD * LL;
    const float* scale = (isT ? csum : rsum) + (size_t)b * LL;
    float* Cb = out + (isT ? NE * 0 + (size_t)NB * LL * DD : 0) + (size_t)b * LL * DD;

    const int r0s = tid >> 2,  kv0 = (tid & 3) * 8;
    const int r1s = r0s + 64;
    const int ar  = tid >> 4,  akv = (tid & 15) * 8;

    auto issue = [&](int ch, int st) {
        const int k0 = ch << 5;
        uint32_t s0 = smb + (uint32_t)st * STG;
        const size_t ob0 = (size_t)(bn + r0s) * LL + k0 + kv0;
        const size_t ob1 = (size_t)(bn + r1s) * LL + k0 + kv0;
        if (isT) {
            const size_t oa0 = (size_t)(k0 + ar) * LL + bm + akv;
            const size_t oa1 = (size_t)(k0 + ar + 16) * LL + bm + akv;
            cp_async16(s0        + ar * 272 + akv * 2,        Ah + oa0);
            cp_async16(s0        + (ar + 16) * 272 + akv * 2, Ah + oa1);
            cp_async16(s0 + 8704 + ar * 272 + akv * 2,        Al + oa0);
            cp_async16(s0 + 8704 + (ar + 16) * 272 + akv * 2, Al + oa1);
            cp_async16(s0 + 17408 + r0s * 80 + kv0 * 2, Bh + ob0);
            cp_async16(s0 + 17408 + r1s * 80 + kv0 * 2, Bh + ob1);
            cp_async16(s0 + 27648 + r0s * 80 + kv0 * 2, Bl + ob0);
            cp_async16(s0 + 27648 + r1s * 80 + kv0 * 2, Bl + ob1);
        } else {
            const size_t oa0 = (size_t)(bm + r0s) * LL + k0 + kv0;
            const size_t oa1 = (size_t)(bm + r1s) * LL + k0 + kv0;
            cp_async16(s0         + r0s * 80 + kv0 * 2, Ah + oa0);
            cp_async16(s0         + r1s * 80 + kv0 * 2, Ah + oa1);
            cp_async16(s0 + 10240 + r0s * 80 + kv0 * 2, Al + oa0);
            cp_async16(s0 + 10240 + r1s * 80 + kv0 * 2, Al + oa1);
            cp_async16(s0 + 20480 + r0s * 80 + kv0 * 2, Bh + ob0);
            cp_async16(s0 + 20480 + r1s * 80 + kv0 * 2, Bh + ob1);
            cp_async16(s0 + 30720 + r0s * 80 + kv0 * 2, Bl + ob0);
            cp_async16(s0 + 30720 + r1s * 80 + kv0 * 2, Bl + ob1);
        }
        asm volatile("cp.async.commit_group;");
    };

    float acc[2][8][4] = {};
    issue(0, 0);
    for (int ch = 0; ch < nch; ch++) {
        const int st = ch & 1;
        if (ch + 1 < nch) { issue(ch + 1, st ^ 1); asm volatile("cp.async.wait_group 1;"); }
        else              { asm volatile("cp.async.wait_group 0;"); }
        __syncthreads();
        const uint32_t s0 = smb + (uint32_t)st * STG;
        if (isT) {
            #pragma unroll
            for (int ks = 0; ks < 2; ks++) {
                const uint32_t atrow = (uint32_t)(ks * 16 + ((lane >> 4) << 3) + (lane & 7)) * 272;
                const uint32_t acol0 = (uint32_t)(wm * 32 + ((lane >> 3) & 1) * 8) * 2;
                const uint32_t colb  = (uint32_t)(ks * 16 + (lane >> 4) * 8) * 2;
                const uint32_t brow  = (uint32_t)(wn * 64 + (lane & 15)) * 80 + colb;
                uint32_t ah[2][4];
                ldsm4t(ah[0], s0 + atrow + acol0);
                ldsm4t(ah[1], s0 + atrow + acol0 + 32);
                uint32_t bh[4][4];
                #pragma unroll
                for (int fn = 0; fn < 4; fn++)
                    ldsm4(bh[fn], s0 + 17408 + brow + fn * 16 * 80);
                #pragma unroll
                for (int fm = 0; fm < 2; fm++)
                    #pragma unroll
                    for (int fn = 0; fn < 4; fn++) {
                        mma_bf16(acc[fm][fn * 2],     ah[fm], bh[fn][0], bh[fn][2]);
                        mma_bf16(acc[fm][fn * 2 + 1], ah[fm], bh[fn][1], bh[fn][3]);
                    }
                uint32_t al[2][4];
                ldsm4t(al[0], s0 + 8704 + atrow + acol0);
                ldsm4t(al[1], s0 + 8704 + atrow + acol0 + 32);
                #pragma unroll
                for (int fm = 0; fm < 2; fm++)
                    #pragma unroll
                    for (int fn = 0; fn < 4; fn++) {
                        mma_bf16(acc[fm][fn * 2],     al[fm], bh[fn][0], bh[fn][2]);
                        mma_bf16(acc[fm][fn * 2 + 1], al[fm], bh[fn][1], bh[fn][3]);
                    }
                uint32_t bl[4][4];
                #pragma unroll
                for (int fn = 0; fn < 4; fn++)
                    ldsm4(bl[fn], s0 + 27648 + brow + fn * 16 * 80);
                #pragma unroll
                for (int fm = 0; fm < 2; fm++)
                    #pragma unroll
                    for (int fn = 0; fn < 4; fn++) {
                        mma_bf16(acc[fm][fn * 2],     ah[fm], bl[fn][0], bl[fn][2]);
                        mma_bf16(acc[fm][fn * 2 + 1], ah[fm], bl[fn][1], bl[fn][3]);
                    }
            }
        } else {
            #pragma unroll
            for (int ks = 0; ks < 2; ks++) {
                const uint32_t colb = (uint32_t)(ks * 16 + (lane >> 4) * 8) * 2;
                const uint32_t arow = (uint32_t)(wm * 32 + (lane & 15)) * 80 + colb;
                const uint32_t brow = (uint32_t)(wn * 64 + (lane & 15)) * 80 + colb;
                uint32_t ah[2][4];
                ldsm4(ah[0], s0 + arow);
                ldsm4(ah[1], s0 + arow + 16 * 80);
                uint32_t bh[4][4];
                #pragma unroll
                for (int fn = 0; fn < 4; fn++)
                    ldsm4(bh[fn], s0 + 20480 + brow + fn * 16 * 80);
                #pragma unroll
                for (int fm = 0; fm < 2; fm++)
                    #pragma unroll
                    for (int fn = 0; fn < 4; fn++) {
                        mma_bf16(acc[fm][fn * 2],     ah[fm], bh[fn][0], bh[fn][2]);
                        mma_bf16(acc[fm][fn * 2 + 1], ah[fm], bh[fn][1], bh[fn][3]);
                    }
                uint32_t al[2][4];
                ldsm4(al[0], s0 + arow + 10240);
                ldsm4(al[1], s0 + arow + 10240 + 16 * 80);
                #pragma unroll
                for (int fm = 0; fm < 2; fm++)
                    #pragma unroll
                    for (int fn = 0; fn < 4; fn++) {
                        mma_bf16(acc[fm][fn * 2],     al[fm], bh[fn][0], bh[fn][2]);
                        mma_bf16(acc[fm][fn * 2 + 1], al[fm], bh[fn][1], bh[fn][3]);
                    }
                uint32_t bl[4][4];
                #pragma unroll
                for (int fn = 0; fn < 4; fn++)
                    ldsm4(bl[fn], s0 + 30720 + brow + fn * 16 * 80);
                #pragma unroll
                for (int fm = 0; fm < 2; fm++)
                    #pragma unroll
                    for (int fn = 0; fn < 4; fn++) {
                        mma_bf16(acc[fm][fn * 2],     ah[fm], bl[fn][0], bl[fn][2]);
                        mma_bf16(acc[fm][fn * 2 + 1], ah[fm], bl[fn][1], bl[fn][3]);
                    }
            }
        }
        __syncthreads();
    }

    const int fr = lane >> 2;
    const int fc = (lane & 3) * 2;
    #pragma unroll
    for (int fm = 0; fm < 2; fm++) {
        const int row0 = bm + wm * 32 + fm * 16 + fr;
        float s0 = 1.0f / scale[row0];
        float s1 = 1.0f / scale[row0 + 8];
        #pragma unroll
        for (int fn = 0; fn < 8; fn++) {
            const int col = bn + wn * 64 + fn * 8 + fc;
            float2 v0, v1;
            v0.x = acc[fm][fn][0] * s0; v0.y = acc[fm][fn][1] * s0;
            v1.x = acc[fm][fn][2] * s1; v1.y = acc[fm][fn][3] * s1;
            *(float2*)(Cb + (size_t)row0 * DD + col) = v0;
            *(float2*)(Cb + (size_t)(row0 + 8) * DD + col) = v1;
        }
    }
}

// ---------------------------------------------------------------------------
// Fused split + transpose-split for P and H in one launch.
// z < NB: input P, normal->Xp, trans->Pt; z >= NB: input H, ->Xh, ->Ht.
// ---------------------------------------------------------------------------
__global__ void split_both_kernel(const float* __restrict__ P, const float* __restrict__ H,
                                  bf16* __restrict__ Xph, bf16* __restrict__ Xpl,
                                  bf16* __restrict__ Xhh, bf16* __restrict__ Xhl,
                                  bf16* __restrict__ Pth, bf16* __restrict__ Ptl,
                                  bf16* __restrict__ Hth, bf16* __restrict__ Htl)
{
    __shared__ float tile[32][33];
    const int z = blockIdx.z;
    const int isH = z >= NB;
    const int b = z & (NB - 1);
    const float* ip = (isH ? H : P) + (size_t)b * LL * DD;
    bf16* nh = (isH ? Xhh : Xph) + (size_t)b * LL * DD;
    bf16* nl = (isH ? Xhl : Xpl) + (size_t)b * LL * DD;
    bf16* th = (isH ? Hth : Pth) + (size_t)b * DD * LL;
    bf16* tl = (isH ? Htl : Ptl) + (size_t)b * DD * LL;

    const int c0 = blockIdx.x * 32, r0 = blockIdx.y * 32;
    const int tx = threadIdx.x, ty = threadIdx.y;
    #pragma unroll
    for (int i = ty; i < 32; i += 8) {
        float v = ip[(size_t)(r0 + i) * DD + c0 + tx];
        tile[i][tx] = v;
        bf16 h = __float2bfloat16(v);
        size_t o = (size_t)(r0 + i) * DD + c0 + tx;
        nh[o] = h;
        nl[o] = __float2bfloat16(v - __bfloat162float(h));
    }
    __syncthreads();
    #pragma unroll
    for (int i = ty; i < 32; i += 8) {
        float v = tile[tx][i];
        bf16 h = __float2bfloat16(v);
        size_t o = (size_t)(c0 + i) * LL + r0 + tx;
        th[o] = h;
        tl[o] = __float2bfloat16(v - __bfloat162float(h));
    }
}

// W transpose + split (small, once)
__global__ void transpose_split_kernel(const float* __restrict__ in, bf16* __restrict__ ohi,
                                       bf16* __restrict__ olo, int R, int C)
{
    __shared__ float tile[32][33];
    int c0 = blockIdx.x * 32, r0 = blockIdx.y * 32;
    int tx = threadIdx.x, ty = threadIdx.y;
    #pragma unroll
    for (int i = ty; i < 32; i += 8)
        tile[i][tx] = in[(size_t)(r0 + i) * C + c0 + tx];
    __syncthreads();
    #pragma unroll
    for (int i = ty; i < 32; i += 8) {
        float v = tile[tx][i];
        bf16 h = __float2bfloat16(v);
        size_t o = (size_t)(c0 + i) * R + r0 + tx;
        ohi[o] = h;
        olo[o] = __float2bfloat16(v - __bfloat162float(h));
    }
}

__global__ void initstats_kernel() {
    int i = blockIdx.x * 256 + threadIdx.x;
    if (i < NB * LL) { g_rowsum[i] = 0.f; g_colsum[i] = 0.f; }
}

// ---------------------------------------------------------------------------
#define SYM(p, s) do { void* _t; cudaGetSymbolAddress(&_t, s); p = decltype(p)(_t); } while (0)

extern "C" void kernel_launch(void* const* d_in, const int* in_sizes, int n_in,
                              void* d_out, int out_size) {
    const float* P   = (const float*)d_in[0];
    const float* Hyp = (const float*)d_in[1];
    const float* W   = (const float*)d_in[2];
    float* out = (float*)d_out;

    bf16 *Xph, *Xpl, *Xhh, *Xhl, *Wth, *Wtl, *Fph, *Fpl, *Fhh, *Fhl;
    bf16 *Hth, *Htl, *Pth, *Ptl, *Trh, *Trl;
    float *rsum, *csum;
    SYM(Xph, g_Xp_hi); SYM(Xpl, g_Xp_lo); SYM(Xhh, g_Xh_hi); SYM(Xhl, g_Xh_lo);
    SYM(Wth, g_Wt_hi); SYM(Wtl, g_Wt_lo);
    SYM(Fph, g_Fp_hi); SYM(Fpl, g_Fp_lo); SYM(Fhh, g_Fh_hi); SYM(Fhl, g_Fh_lo);
    SYM(Hth, g_Ht_hi); SYM(Htl, g_Ht_lo); SYM(Pth, g_Pt_hi); SYM(Ptl, g_Pt_lo);
    SYM(Trh, g_Tr_hi); SYM(Trl, g_Tr_lo);
    SYM(rsum, g_rowsum); SYM(csum, g_colsum);

    static int attr_done = 0;
    if (!attr_done) {
        cudaFuncSetAttribute(gemm_split, cudaFuncAttributeMaxDynamicSharedMemorySize, 2 * STG);
        cudaFuncSetAttribute(gemm_tail,  cudaFuncAttributeMaxDynamicSharedMemorySize, 2 * STG);
        attr_done = 1;
    }

    dim3 t256(256), t32x8(32, 8);
    const int SMG = 2 * STG;

    // fused input conversion: split + transpose-split for P and H, one launch
    split_both_kernel<<<dim3(8, 32, 2 * NB), t32x8>>>(P, Hyp, Xph, Xpl, Xhh, Xhl,
                                                      Pth, Ptl, Hth, Htl);
    transpose_split_kernel<<<dim3(8, 8, 1), t32x8>>>(W, Wth, Wtl, DD, HH);
    initstats_kernel<<<128, t256>>>();

    // proj (merged): z=0 -> Fp = tanh(Xp@W), z=1 -> Fh = tanh(Xh@W)
    gemm_split<<<dim3(256, 2, 2), t256, SMG>>>(Xph, Xpl, 0, DD, Wth, Wtl, 0, DD, DD, 1,
                                               Fph, Fpl, 0, HH, nullptr, nullptr,
                                               Xhh, Xhl, Fhh, Fhl);

    // eij -> Tr = exp(Fp@Fh^T) (split bf16) + row/col sums
    gemm_split<<<dim3(8, 8, NB), t256, SMG>>>(Fph, Fpl, (size_t)LL * DD, HH,
                                              Fhh, Fhl, (size_t)LL * DD, HH, HH, 3,
                                              Trh, Trl, (size_t)LL * LL, LL, rsum, csum,
                                              nullptr, nullptr, nullptr, nullptr);

    // merged tail: z<NB betas = (Tr@Ht)/rsum, z>=NB alphas = (Tr^T@Pt)/csum
    gemm_tail<<<dim3(8, 2, 2 * NB), t256, SMG>>>(Trh, Trl, Hth, Htl, Pth, Ptl,
                                                 out, rsum, csum);
}